// round 1
// baseline (speedup 1.0000x reference)
#include <cuda_runtime.h>
#include <cstdint>

// ---------------- problem-size bounds (from reference) ----------------
#define MAXN 100000
#define MAXE 1600000
#define MAXH 256
#define MAXG 64

// ---------------- scratch (device globals: allocation-free) ----------------
__device__ float g_bufA[(size_t)MAXN * MAXH];   // ping
__device__ float g_bufB[(size_t)MAXN * MAXH];   // pong
__device__ float g_dis[MAXN];                   // deg_inv_sqrt
__device__ int   g_hist[MAXN];                  // in-degree (from dst)
__device__ int   g_off[MAXN + 1];               // CSR row offsets
__device__ int   g_cursor[MAXN];                // fill cursors
__device__ int   g_csr_src[MAXE];               // src node per CSR slot
__device__ float g_cnt[MAXG];                   // nodes per graph

// ---------------- degree histogram ----------------
__global__ void k_zero_hist(int n) {
    int i = blockIdx.x * blockDim.x + threadIdx.x;
    if (i < n) g_hist[i] = 0;
}

__global__ void k_hist(const int* __restrict__ ei, int E) {
    int e = blockIdx.x * blockDim.x + threadIdx.x;
    if (e < E) atomicAdd(&g_hist[ei[E + e]], 1);   // dst row
}

// single-block exclusive scan over hist -> off/cursor, plus dis = rsqrt(deg+1)
__global__ void k_scan(int n, int E) {
    __shared__ int sh[1024];
    __shared__ int carry;
    if (threadIdx.x == 0) carry = 0;
    __syncthreads();
    for (int base = 0; base < n; base += 1024) {
        int i = base + (int)threadIdx.x;
        int v = (i < n) ? g_hist[i] : 0;
        sh[threadIdx.x] = v;
        __syncthreads();
        for (int ofs = 1; ofs < 1024; ofs <<= 1) {
            int t = (threadIdx.x >= (unsigned)ofs) ? sh[threadIdx.x - ofs] : 0;
            __syncthreads();
            sh[threadIdx.x] += t;
            __syncthreads();
        }
        int incl = sh[threadIdx.x];
        int excl = incl - v;
        if (i < n) {
            int o = carry + excl;
            g_off[i] = o;
            g_cursor[i] = o;
            g_dis[i] = rsqrtf((float)v + 1.0f);
        }
        __syncthreads();
        if (threadIdx.x == 1023) carry += sh[1023];
        __syncthreads();
    }
    if (threadIdx.x == 0) g_off[n] = E;
}

__global__ void k_fill(const int* __restrict__ ei, int E) {
    int e = blockIdx.x * blockDim.x + threadIdx.x;
    if (e < E) {
        int s = ei[e];
        int d = ei[E + e];
        int pos = atomicAdd(&g_cursor[d], 1);
        g_csr_src[pos] = s;
    }
}

// ---------------- tiled fp32 GEMM:  C[M,Nn] = A[M,K] @ W[K,Nn] (+bias) ----------------
#define BM 64
#define BN 64
#define BK 16

__global__ __launch_bounds__(256)
void k_gemm(const float* __restrict__ A, const float* __restrict__ W,
            const float* __restrict__ bias, float* __restrict__ C,
            int M, int K, int Nn) {
    __shared__ float As[BK][BM + 4];
    __shared__ float Bs[BK][BN];
    int tid = threadIdx.x;
    int m0 = blockIdx.x * BM;
    int n0 = blockIdx.y * BN;
    int tx = tid & 15;        // 0..15 -> 4 cols each
    int ty = tid >> 4;        // 0..15 -> 4 rows each
    int aRow = tid >> 2;      // 0..63
    int aCol = (tid & 3) * 4; // 0,4,8,12
    int bRow = tid >> 4;      // 0..15
    int bCol = (tid & 15) * 4;

    float acc[4][4] = {};
    for (int k0 = 0; k0 < K; k0 += BK) {
        float4 av = make_float4(0.f, 0.f, 0.f, 0.f);
        int gr = m0 + aRow;
        if (gr < M) av = *(const float4*)(A + (size_t)gr * K + k0 + aCol);
        As[aCol + 0][aRow] = av.x;
        As[aCol + 1][aRow] = av.y;
        As[aCol + 2][aRow] = av.z;
        As[aCol + 3][aRow] = av.w;
        float4 bv = *(const float4*)(W + (size_t)(k0 + bRow) * Nn + n0 + bCol);
        *(float4*)&Bs[bRow][bCol] = bv;
        __syncthreads();
#pragma unroll
        for (int k = 0; k < BK; k++) {
            float a[4], b[4];
#pragma unroll
            for (int i = 0; i < 4; i++) a[i] = As[k][ty * 4 + i];
#pragma unroll
            for (int j = 0; j < 4; j++) b[j] = Bs[k][tx * 4 + j];
#pragma unroll
            for (int i = 0; i < 4; i++)
#pragma unroll
                for (int j = 0; j < 4; j++) acc[i][j] += a[i] * b[j];
        }
        __syncthreads();
    }
#pragma unroll
    for (int i = 0; i < 4; i++) {
        int r = m0 + ty * 4 + i;
        if (r >= M) continue;
        float4 o = make_float4(acc[i][0], acc[i][1], acc[i][2], acc[i][3]);
        if (bias) {
            o.x += bias[n0 + tx * 4 + 0];
            o.y += bias[n0 + tx * 4 + 1];
            o.z += bias[n0 + tx * 4 + 2];
            o.w += bias[n0 + tx * 4 + 3];
        }
        *(float4*)(C + (size_t)r * Nn + n0 + tx * 4) = o;
    }
}

// ---------------- fused CSR gather + self-loop + bias + relu ----------------
// one warp per dst node; lane holds HH/128 float4 accumulators
template <int HH, bool RELU>
__global__ __launch_bounds__(256)
void k_aggregate(const float* __restrict__ h, const float* __restrict__ bias,
                 float* __restrict__ out, int n) {
    int warp = (blockIdx.x * blockDim.x + threadIdx.x) >> 5;
    int lane = threadIdx.x & 31;
    if (warp >= n) return;
    int d = warp;
    float disd = g_dis[d];
    int start = g_off[d];
    int end = g_off[d + 1];
    constexpr int V = HH / 128;
    float4 acc[V];
    // self-loop term: h[d] * dis^2
    {
        float sn = disd * disd;
        const float4* hp = (const float4*)(h + (size_t)d * HH);
#pragma unroll
        for (int v = 0; v < V; v++) {
            float4 hv = hp[lane + 32 * v];
            acc[v] = make_float4(hv.x * sn, hv.y * sn, hv.z * sn, hv.w * sn);
        }
    }
    for (int j = start; j < end; j++) {
        int s = g_csr_src[j];
        float nrm = disd * g_dis[s];
        const float4* hp = (const float4*)(h + (size_t)s * HH);
#pragma unroll
        for (int v = 0; v < V; v++) {
            float4 hv = hp[lane + 32 * v];
            acc[v].x += hv.x * nrm;
            acc[v].y += hv.y * nrm;
            acc[v].z += hv.z * nrm;
            acc[v].w += hv.w * nrm;
        }
    }
    float4* op = (float4*)(out + (size_t)d * HH);
    const float4* bp = (const float4*)bias;
#pragma unroll
    for (int v = 0; v < V; v++) {
        float4 bb = bp[lane + 32 * v];
        float4 r = make_float4(acc[v].x + bb.x, acc[v].y + bb.y,
                               acc[v].z + bb.z, acc[v].w + bb.w);
        if (RELU) {
            r.x = fmaxf(r.x, 0.f);
            r.y = fmaxf(r.y, 0.f);
            r.z = fmaxf(r.z, 0.f);
            r.w = fmaxf(r.w, 0.f);
        }
        op[lane + 32 * v] = r;
    }
}

// ---------------- pooling ----------------
__global__ void k_zero_pool(float* __restrict__ out, int total, int G) {
    int i = blockIdx.x * blockDim.x + threadIdx.x;
    if (i < total) out[i] = 0.f;
    if (i < G) g_cnt[i] = 0.f;
}

// blockDim = 128 (one thread per feature), each block scans 256 sorted nodes
__global__ __launch_bounds__(128)
void k_pool(const float* __restrict__ P, const float* __restrict__ Q,
            const int* __restrict__ batch, float* __restrict__ out, int n) {
    int f = threadIdx.x;
    int base = blockIdx.x * 256;
    float acc = 0.f;
    float cnt = 0.f;
    int cur = -1;
    for (int k = 0; k < 256; k++) {
        int i = base + k;
        if (i >= n) break;
        int g = batch[i];
        if (g != cur) {
            if (cur >= 0) {
                atomicAdd(&out[cur * 128 + f], acc);
                if (f == 0) atomicAdd(&g_cnt[cur], cnt);
            }
            cur = g;
            acc = 0.f;
            cnt = 0.f;
        }
        acc += P[(size_t)i * 128 + f] + Q[(size_t)i * 128 + f];
        cnt += 1.f;
    }
    if (cur >= 0) {
        atomicAdd(&out[cur * 128 + f], acc);
        if (f == 0) atomicAdd(&g_cnt[cur], cnt);
    }
}

__global__ void k_div(float* __restrict__ out, int total) {
    int i = blockIdx.x * blockDim.x + threadIdx.x;
    if (i < total) {
        int g = i >> 7;
        out[i] /= fmaxf(g_cnt[g], 1.0f);
    }
}

// ---------------- launch ----------------
extern "C" void kernel_launch(void* const* d_in, const int* in_sizes, int n_in,
                              void* d_out, int out_size) {
    const float* x     = (const float*)d_in[0];
    const int*   ei    = (const int*)d_in[1];
    const int*   batch = (const int*)d_in[2];
    const float* W1 = (const float*)d_in[3];
    const float* b1 = (const float*)d_in[4];
    const float* W2 = (const float*)d_in[5];
    const float* b2 = (const float*)d_in[6];
    const float* W3 = (const float*)d_in[7];
    const float* b3 = (const float*)d_in[8];
    const float* W4 = (const float*)d_in[9];
    const float* b4 = (const float*)d_in[10];
    const float* Wl = (const float*)d_in[11];
    const float* bl = (const float*)d_in[12];
    float* out = (float*)d_out;

    const int F = 128, H = 128;
    int N = in_sizes[0] / F;
    int E = in_sizes[1] / 2;
    int G = out_size / H;

    float *bufA = nullptr, *bufB = nullptr;
    cudaGetSymbolAddress((void**)&bufA, g_bufA);
    cudaGetSymbolAddress((void**)&bufB, g_bufB);

    // ---- CSR build + normalization ----
    k_zero_hist<<<(N + 255) / 256, 256>>>(N);
    k_hist<<<(E + 255) / 256, 256>>>(ei, E);
    k_scan<<<1, 1024>>>(N, E);
    k_fill<<<(E + 255) / 256, 256>>>(ei, E);

    dim3 g128((N + BM - 1) / BM, 128 / BN);
    dim3 g256((N + BM - 1) / BM, 256 / BN);
    int aggBlocks = (N * 32 + 255) / 256;

    // ---- layer 1: x(128) -> 128, relu ----
    k_gemm<<<g128, 256>>>(x, W1, nullptr, bufA, N, 128, 128);
    k_aggregate<128, true><<<aggBlocks, 256>>>(bufA, b1, bufB, N);
    // ---- layer 2: 128 -> 128, relu ----
    k_gemm<<<g128, 256>>>(bufB, W2, nullptr, bufA, N, 128, 128);
    k_aggregate<128, true><<<aggBlocks, 256>>>(bufA, b2, bufB, N);
    // ---- layer 3: 128 -> 256, relu ----
    k_gemm<<<g256, 256>>>(bufB, W3, nullptr, bufA, N, 128, 256);
    k_aggregate<256, true><<<aggBlocks, 256>>>(bufA, b3, bufB, N);
    // ---- layer 4: 256 -> 128, no relu ----
    k_gemm<<<g128, 256>>>(bufB, W4, nullptr, bufA, N, 256, 128);
    k_aggregate<128, false><<<aggBlocks, 256>>>(bufA, b4, bufB, N);
    // ---- residual linear: x @ Wl + bl ----
    k_gemm<<<g128, 256>>>(x, Wl, bl, bufA, N, 128, 128);

    // ---- global mean pool ----
    k_zero_pool<<<(out_size + 255) / 256, 256>>>(out, out_size, G);
    k_pool<<<(N + 255) / 256, 128>>>(bufB, bufA, batch, out, N);
    k_div<<<(out_size + 255) / 256, 256>>>(out, out_size);
}

// round 2
// speedup vs baseline: 1.5380x; 1.5380x over previous
#include <cuda_runtime.h>
#include <cstdint>

// ---------------- problem-size bounds ----------------
#define MAXN 100000
#define MAXE 1600000
#define MAXH 256
#define MAXG 64

// ---------------- scratch (device globals: allocation-free) ----------------
__device__ float g_bufA[(size_t)MAXN * MAXH];
__device__ float g_bufB[(size_t)MAXN * MAXH];
__device__ float g_dis[MAXN];
__device__ int   g_hist[MAXN];
__device__ int   g_off[MAXN + 1];
__device__ int   g_cursor[MAXN];
__device__ int   g_csr_src[MAXE];
__device__ float g_cnt[MAXG];

// ---------------- degree histogram / CSR ----------------
__global__ void k_zero_hist(int n) {
    int i = blockIdx.x * blockDim.x + threadIdx.x;
    if (i < n) g_hist[i] = 0;
}

__global__ void k_hist(const int* __restrict__ ei, int E) {
    int e = blockIdx.x * blockDim.x + threadIdx.x;
    if (e < E) atomicAdd(&g_hist[ei[E + e]], 1);
}

__global__ void k_scan(int n, int E) {
    __shared__ int sh[1024];
    __shared__ int carry;
    if (threadIdx.x == 0) carry = 0;
    __syncthreads();
    for (int base = 0; base < n; base += 1024) {
        int i = base + (int)threadIdx.x;
        int v = (i < n) ? g_hist[i] : 0;
        sh[threadIdx.x] = v;
        __syncthreads();
        for (int ofs = 1; ofs < 1024; ofs <<= 1) {
            int t = (threadIdx.x >= (unsigned)ofs) ? sh[threadIdx.x - ofs] : 0;
            __syncthreads();
            sh[threadIdx.x] += t;
            __syncthreads();
        }
        int incl = sh[threadIdx.x];
        int excl = incl - v;
        if (i < n) {
            int o = carry + excl;
            g_off[i] = o;
            g_cursor[i] = o;
            g_dis[i] = rsqrtf((float)v + 1.0f);
        }
        __syncthreads();
        if (threadIdx.x == 1023) carry += sh[1023];
        __syncthreads();
    }
    if (threadIdx.x == 0) g_off[n] = E;
}

__global__ void k_fill(const int* __restrict__ ei, int E) {
    int e = blockIdx.x * blockDim.x + threadIdx.x;
    if (e < E) {
        int s = ei[e];
        int d = ei[E + e];
        int pos = atomicAdd(&g_cursor[d], 1);
        g_csr_src[pos] = s;
    }
}

// ---------------- TF32 tensor-core GEMM ----------------
// C[M,Nn] = A[M,K] @ W[K,Nn] (+bias) (+relu)
// block tile 128x128, BK=32, 8 warps (4m x 2n), warp tile 32x64
__device__ __forceinline__ void mma_tf32(float* d, const uint32_t* a, const uint32_t* b) {
    asm volatile(
        "mma.sync.aligned.m16n8k8.row.col.f32.tf32.tf32.f32 "
        "{%0,%1,%2,%3}, {%4,%5,%6,%7}, {%8,%9}, {%0,%1,%2,%3};"
        : "+f"(d[0]), "+f"(d[1]), "+f"(d[2]), "+f"(d[3])
        : "r"(a[0]), "r"(a[1]), "r"(a[2]), "r"(a[3]), "r"(b[0]), "r"(b[1]));
}

__device__ __forceinline__ uint32_t f2tf32(float f) {
    uint32_t r;
    asm("cvt.rna.tf32.f32 %0, %1;" : "=r"(r) : "f"(f));
    return r;
}

template <bool RELU>
__global__ __launch_bounds__(256)
void k_gemm_tf32(const float* __restrict__ A, const float* __restrict__ W,
                 const float* __restrict__ bias, float* __restrict__ C,
                 int M, int K, int Nn) {
    __shared__ uint32_t As[128 * 32];   // [m][k], k-group XOR-swizzled by (m&7)
    __shared__ uint32_t Bs[32 * 128];   // [k][n], n-group XOR-swizzled by ((2k)&7)
    int tid = threadIdx.x;
    int lane = tid & 31;
    int w = tid >> 5;
    int wm = w & 3;
    int wn = w >> 2;
    int m0 = blockIdx.x * 128;
    int n0 = blockIdx.y * 128;

    float acc[2][8][4];
#pragma unroll
    for (int mi = 0; mi < 2; mi++)
#pragma unroll
        for (int nj = 0; nj < 8; nj++)
#pragma unroll
            for (int q = 0; q < 4; q++) acc[mi][nj][q] = 0.f;

    for (int kt = 0; kt < K; kt += 32) {
        // stage A tile (coalesced LDG.128, conflict-free swizzled STS.128)
#pragma unroll
        for (int it = 0; it < 4; it++) {
            int idx = it * 256 + tid;
            int m = idx >> 3;          // 0..127
            int gk = idx & 7;          // k-group of 4
            float4 v = make_float4(0.f, 0.f, 0.f, 0.f);
            if (m0 + m < M) v = *(const float4*)(A + (size_t)(m0 + m) * K + kt + gk * 4);
            uint4 t;
            t.x = f2tf32(v.x); t.y = f2tf32(v.y); t.z = f2tf32(v.z); t.w = f2tf32(v.w);
            *(uint4*)&As[m * 32 + ((gk ^ (m & 7)) << 2)] = t;
        }
        // stage B tile
#pragma unroll
        for (int it = 0; it < 4; it++) {
            int idx = it * 256 + tid;
            int k = idx >> 5;          // 0..31
            int gn = idx & 31;         // n-group of 4
            float4 v = *(const float4*)(W + (size_t)(kt + k) * Nn + n0 + gn * 4);
            uint4 t;
            t.x = f2tf32(v.x); t.y = f2tf32(v.y); t.z = f2tf32(v.z); t.w = f2tf32(v.w);
            *(uint4*)&Bs[k * 128 + ((gn ^ ((k << 1) & 7)) << 2)] = t;
        }
        __syncthreads();

#pragma unroll
        for (int kc = 0; kc < 4; kc++) {
            uint32_t a[2][4];
#pragma unroll
            for (int mi = 0; mi < 2; mi++) {
                int r = wm * 32 + mi * 16 + (lane >> 2);
                int c = kc * 8 + (lane & 3);
                int c4 = c + 4;
                a[mi][0] = As[r * 32 + ((((c >> 2) ^ (r & 7))) << 2) + (c & 3)];
                a[mi][1] = As[(r + 8) * 32 + ((((c >> 2) ^ (r & 7))) << 2) + (c & 3)];
                a[mi][2] = As[r * 32 + ((((c4 >> 2) ^ (r & 7))) << 2) + (c4 & 3)];
                a[mi][3] = As[(r + 8) * 32 + ((((c4 >> 2) ^ (r & 7))) << 2) + (c4 & 3)];
            }
            uint32_t b[8][2];
#pragma unroll
            for (int nj = 0; nj < 8; nj++) {
                int kk = kc * 8 + (lane & 3);
                int k4 = kk + 4;
                int n = wn * 64 + nj * 8 + (lane >> 2);
                b[nj][0] = Bs[kk * 128 + ((((n >> 2) ^ ((kk << 1) & 7))) << 2) + (n & 3)];
                b[nj][1] = Bs[k4 * 128 + ((((n >> 2) ^ ((k4 << 1) & 7))) << 2) + (n & 3)];
            }
#pragma unroll
            for (int mi = 0; mi < 2; mi++)
#pragma unroll
                for (int nj = 0; nj < 8; nj++)
                    mma_tf32(acc[mi][nj], a[mi], b[nj]);
        }
        __syncthreads();
    }

    // epilogue
#pragma unroll
    for (int mi = 0; mi < 2; mi++) {
        int r = m0 + wm * 32 + mi * 16 + (lane >> 2);
#pragma unroll
        for (int nj = 0; nj < 8; nj++) {
            int cn = n0 + wn * 64 + nj * 8 + 2 * (lane & 3);
            float bx = 0.f, by = 0.f;
            if (bias) { bx = bias[cn]; by = bias[cn + 1]; }
            float2 v0 = make_float2(acc[mi][nj][0] + bx, acc[mi][nj][1] + by);
            float2 v1 = make_float2(acc[mi][nj][2] + bx, acc[mi][nj][3] + by);
            if (RELU) {
                v0.x = fmaxf(v0.x, 0.f); v0.y = fmaxf(v0.y, 0.f);
                v1.x = fmaxf(v1.x, 0.f); v1.y = fmaxf(v1.y, 0.f);
            }
            if (r < M)     *(float2*)(C + (size_t)r * Nn + cn) = v0;
            if (r + 8 < M) *(float2*)(C + (size_t)(r + 8) * Nn + cn) = v1;
        }
    }
}

// ---------------- fused CSR gather + self-loop (+bias) (+relu) ----------------
template <int HH, bool RELU>
__global__ __launch_bounds__(256)
void k_aggregate(const float* __restrict__ h, const float* __restrict__ bias,
                 float* __restrict__ out, int n) {
    int warp = (blockIdx.x * blockDim.x + threadIdx.x) >> 5;
    int lane = threadIdx.x & 31;
    if (warp >= n) return;
    int d = warp;
    float disd = g_dis[d];
    int start = g_off[d];
    int end = g_off[d + 1];
    constexpr int V = HH / 128;
    float4 acc[V];
    {
        float sn = disd * disd;
        const float4* hp = (const float4*)(h + (size_t)d * HH);
#pragma unroll
        for (int v = 0; v < V; v++) {
            float4 hv = hp[lane + 32 * v];
            acc[v] = make_float4(hv.x * sn, hv.y * sn, hv.z * sn, hv.w * sn);
        }
    }
    for (int j = start; j < end; j++) {
        int s = g_csr_src[j];
        float nrm = disd * g_dis[s];
        const float4* hp = (const float4*)(h + (size_t)s * HH);
#pragma unroll
        for (int v = 0; v < V; v++) {
            float4 hv = hp[lane + 32 * v];
            acc[v].x += hv.x * nrm;
            acc[v].y += hv.y * nrm;
            acc[v].z += hv.z * nrm;
            acc[v].w += hv.w * nrm;
        }
    }
    float4* op = (float4*)(out + (size_t)d * HH);
    const float4* bp = (const float4*)bias;
#pragma unroll
    for (int v = 0; v < V; v++) {
        float4 bb = make_float4(0.f, 0.f, 0.f, 0.f);
        if (bias) bb = bp[lane + 32 * v];
        float4 r = make_float4(acc[v].x + bb.x, acc[v].y + bb.y,
                               acc[v].z + bb.z, acc[v].w + bb.w);
        if (RELU) {
            r.x = fmaxf(r.x, 0.f);
            r.y = fmaxf(r.y, 0.f);
            r.z = fmaxf(r.z, 0.f);
            r.w = fmaxf(r.w, 0.f);
        }
        op[lane + 32 * v] = r;
    }
}

// ---------------- pooling ----------------
__global__ void k_zero_pool(float* __restrict__ out, int total, int G) {
    int i = blockIdx.x * blockDim.x + threadIdx.x;
    if (i < total) out[i] = 0.f;
    if (i < G) g_cnt[i] = 0.f;
}

__global__ __launch_bounds__(128)
void k_pool(const float* __restrict__ P, const float* __restrict__ Q,
            const int* __restrict__ batch, float* __restrict__ out, int n) {
    int f = threadIdx.x;
    int base = blockIdx.x * 256;
    float acc = 0.f;
    float cnt = 0.f;
    int cur = -1;
    for (int k = 0; k < 256; k++) {
        int i = base + k;
        if (i >= n) break;
        int g = batch[i];
        if (g != cur) {
            if (cur >= 0) {
                atomicAdd(&out[cur * 128 + f], acc);
                if (f == 0) atomicAdd(&g_cnt[cur], cnt);
            }
            cur = g;
            acc = 0.f;
            cnt = 0.f;
        }
        acc += P[(size_t)i * 128 + f] + Q[(size_t)i * 128 + f];
        cnt += 1.f;
    }
    if (cur >= 0) {
        atomicAdd(&out[cur * 128 + f], acc);
        if (f == 0) atomicAdd(&g_cnt[cur], cnt);
    }
}

__global__ void k_div(float* __restrict__ out, int total) {
    int i = blockIdx.x * blockDim.x + threadIdx.x;
    if (i < total) {
        int g = i >> 7;
        out[i] /= fmaxf(g_cnt[g], 1.0f);
    }
}

// ---------------- launch ----------------
extern "C" void kernel_launch(void* const* d_in, const int* in_sizes, int n_in,
                              void* d_out, int out_size) {
    const float* x     = (const float*)d_in[0];
    const int*   ei    = (const int*)d_in[1];
    const int*   batch = (const int*)d_in[2];
    const float* W1 = (const float*)d_in[3];
    const float* b1 = (const float*)d_in[4];
    const float* W2 = (const float*)d_in[5];
    const float* b2 = (const float*)d_in[6];
    const float* W3 = (const float*)d_in[7];
    const float* b3 = (const float*)d_in[8];
    const float* W4 = (const float*)d_in[9];
    const float* b4 = (const float*)d_in[10];
    const float* Wl = (const float*)d_in[11];
    const float* bl = (const float*)d_in[12];
    float* out = (float*)d_out;

    const int F = 128, H = 128;
    int N = in_sizes[0] / F;
    int E = in_sizes[1] / 2;
    int G = out_size / H;

    float *bufA = nullptr, *bufB = nullptr;
    cudaGetSymbolAddress((void**)&bufA, g_bufA);
    cudaGetSymbolAddress((void**)&bufB, g_bufB);

    // ---- CSR build + normalization ----
    k_zero_hist<<<(N + 255) / 256, 256>>>(N);
    k_hist<<<(E + 255) / 256, 256>>>(ei, E);
    k_scan<<<1, 1024>>>(N, E);
    k_fill<<<(E + 255) / 256, 256>>>(ei, E);

    int MB = (N + 127) / 128;
    int aggBlocks = (N * 32 + 255) / 256;

    // ---- layer 1: gemm(x,W1) -> agg(+b1, relu) ----
    k_gemm_tf32<false><<<dim3(MB, 1), 256>>>(x, W1, nullptr, bufA, N, 128, 128);
    k_aggregate<128, true><<<aggBlocks, 256>>>(bufA, b1, bufB, N);
    // ---- layer 2 ----
    k_gemm_tf32<false><<<dim3(MB, 1), 256>>>(bufB, W2, nullptr, bufA, N, 128, 128);
    k_aggregate<128, true><<<aggBlocks, 256>>>(bufA, b2, bufB, N);
    // ---- layer 3 (reordered: agg first at 128-wide, then gemm 128->256 + b3 + relu) ----
    k_aggregate<128, false><<<aggBlocks, 256>>>(bufB, nullptr, bufA, N);
    k_gemm_tf32<true><<<dim3(MB, 2), 256>>>(bufA, W3, b3, bufB, N, 128, 256);
    // ---- layer 4: gemm 256->128, then agg(+b4) ----
    k_gemm_tf32<false><<<dim3(MB, 1), 256>>>(bufB, W4, nullptr, bufA, N, 256, 128);
    k_aggregate<128, false><<<aggBlocks, 256>>>(bufA, b4, bufB, N);
    // ---- residual: x @ Wl + bl ----
    k_gemm_tf32<false><<<dim3(MB, 1), 256>>>(x, Wl, bl, bufA, N, 128, 128);

    // ---- global mean pool ----
    k_zero_pool<<<(out_size + 255) / 256, 256>>>(out, out_size, G);
    k_pool<<<(N + 255) / 256, 128>>>(bufB, bufA, batch, out, N);
    k_div<<<(out_size + 255) / 256, 256>>>(out, out_size);
}

// round 4
// speedup vs baseline: 1.9066x; 1.2396x over previous
#include <cuda_runtime.h>
#include <cstdint>

// ---------------- problem-size bounds ----------------
#define MAXN 100000
#define MAXE 1600000
#define MAXH 256
#define MAXG 64
#define MAXB ((MAXN + 1023) / 1024)

// ---------------- scratch ----------------
__device__ float g_bufA[(size_t)MAXN * MAXH];
__device__ float g_bufB[(size_t)MAXN * MAXH];
__device__ float g_dis[MAXN];
__device__ int   g_hist[MAXN];
__device__ int   g_off[MAXN + 1];
__device__ int   g_cursor[MAXN];
__device__ int   g_csr_src[MAXE];
__device__ float g_cnt[MAXG];
__device__ int   g_bsum[MAXB];
__device__ int   g_boff[MAXB];

// ---------------- CSR build ----------------
__global__ void k_zero_hist(int n) {
    int i = blockIdx.x * blockDim.x + threadIdx.x;
    if (i < n) g_hist[i] = 0;
}

__global__ void k_hist(const int* __restrict__ ei, int E) {
    int e = blockIdx.x * blockDim.x + threadIdx.x;
    if (e < E) atomicAdd(&g_hist[ei[E + e]], 1);
}

__global__ __launch_bounds__(256) void k_scan1(int n) {
    int b = blockIdx.x, t = threadIdx.x;
    int base = b * 1024;
    int s = 0;
    for (int i = t; i < 1024; i += 256) {
        int idx = base + i;
        if (idx < n) s += g_hist[idx];
    }
    __shared__ int sh[256];
    sh[t] = s;
    __syncthreads();
    for (int o = 128; o > 0; o >>= 1) {
        if (t < o) sh[t] += sh[t + o];
        __syncthreads();
    }
    if (t == 0) g_bsum[b] = sh[0];
}

__global__ __launch_bounds__(1024) void k_scan2(int nb) {
    __shared__ int sh[1024];
    int t = threadIdx.x;
    int v = (t < nb) ? g_bsum[t] : 0;
    sh[t] = v;
    __syncthreads();
    for (int o = 1; o < 1024; o <<= 1) {
        int u = (t >= o) ? sh[t - o] : 0;
        __syncthreads();
        sh[t] += u;
        __syncthreads();
    }
    if (t < nb) g_boff[t] = sh[t] - v;
}

__global__ __launch_bounds__(256) void k_scan3(int n, int E) {
    int b = blockIdx.x, t = threadIdx.x;
    int base = b * 1024 + t * 4;
    int v[4];
    int s = 0;
#pragma unroll
    for (int i = 0; i < 4; i++) {
        int idx = base + i;
        v[i] = (idx < n) ? g_hist[idx] : 0;
        s += v[i];
    }
    __shared__ int sh[256];
    sh[t] = s;
    __syncthreads();
    for (int o = 1; o < 256; o <<= 1) {
        int u = (t >= o) ? sh[t - o] : 0;
        __syncthreads();
        sh[t] += u;
        __syncthreads();
    }
    int excl = sh[t] - s + g_boff[b];
#pragma unroll
    for (int i = 0; i < 4; i++) {
        int idx = base + i;
        if (idx < n) {
            g_off[idx] = excl;
            g_cursor[idx] = excl;
            g_dis[idx] = rsqrtf((float)v[i] + 1.0f);
        }
        excl += v[i];
    }
    if (b == 0 && t == 0) g_off[n] = E;
}

__global__ void k_fill(const int* __restrict__ ei, int E) {
    int e = blockIdx.x * blockDim.x + threadIdx.x;
    if (e < E) {
        int s = ei[e];
        int d = ei[E + e];
        int pos = atomicAdd(&g_cursor[d], 1);
        g_csr_src[pos] = s;
    }
}

// ---------------- TF32 tensor-core GEMM, cp.async double-buffered ----------------
__device__ __forceinline__ void mma_tf32(float* d, const uint32_t* a, const uint32_t* b) {
    asm volatile(
        "mma.sync.aligned.m16n8k8.row.col.f32.tf32.tf32.f32 "
        "{%0,%1,%2,%3}, {%4,%5,%6,%7}, {%8,%9}, {%0,%1,%2,%3};"
        : "+f"(d[0]), "+f"(d[1]), "+f"(d[2]), "+f"(d[3])
        : "r"(a[0]), "r"(a[1]), "r"(a[2]), "r"(a[3]), "r"(b[0]), "r"(b[1]));
}

__device__ __forceinline__ uint32_t f2tf32(float f) {
    uint32_t r;
    asm("cvt.rna.tf32.f32 %0, %1;" : "=r"(r) : "f"(f));
    return r;
}

__device__ __forceinline__ void cp16(float* dst, const float* src, bool pred) {
    uint32_t d = (uint32_t)__cvta_generic_to_shared(dst);
    int sz = pred ? 16 : 0;
    asm volatile("cp.async.cg.shared.global [%0], [%1], 16, %2;\n"
                 :: "r"(d), "l"(src), "r"(sz));
}
#define CP_COMMIT() asm volatile("cp.async.commit_group;\n" ::)
#define CP_WAIT(N)  asm volatile("cp.async.wait_group %0;\n" :: "n"(N))

// Block tile 128x128, BK=32, 8 warps (4m x 2n). grid.y selects weight set
// (dual-weight fusion for x@W1 | x@Wl, and the two halves of wide W3).
template <bool RELU>
__global__ __launch_bounds__(256)
void k_gemm_tf32(const float* __restrict__ A, int lda, int K,
                 const float* __restrict__ W0, const float* __restrict__ W1p, int ldw,
                 const float* __restrict__ b0, const float* __restrict__ b1p,
                 float* __restrict__ C, int ldc, int M) {
    extern __shared__ float smem[];
    float* As = smem;                 // [2][128*32] swizzled fp32
    float* Bs = smem + 2 * 128 * 32;  // [2][32*128] swizzled fp32

    int tid = threadIdx.x;
    int lane = tid & 31;
    int w = tid >> 5;
    int wm = w & 3;
    int wn = w >> 2;
    int m0 = blockIdx.x * 128;
    const float* W = (blockIdx.y == 0) ? W0 : W1p;
    const float* bias = (blockIdx.y == 0) ? b0 : b1p;
    int ncol0 = blockIdx.y * 128;

    float acc[2][8][4];
#pragma unroll
    for (int mi = 0; mi < 2; mi++)
#pragma unroll
        for (int nj = 0; nj < 8; nj++)
#pragma unroll
            for (int q = 0; q < 4; q++) acc[mi][nj][q] = 0.f;

    auto stage = [&](int buf, int kt) {
        float* Ab = As + buf * 4096;
        float* Bb = Bs + buf * 4096;
#pragma unroll
        for (int it = 0; it < 4; it++) {
            int idx = it * 256 + tid;
            int m = idx >> 3;
            int gk = idx & 7;
            bool pred = (m0 + m) < M;
            const float* src = pred ? (A + (size_t)(m0 + m) * lda + kt + gk * 4) : A;
            cp16(Ab + m * 32 + ((gk ^ (m & 7)) << 2), src, pred);
        }
#pragma unroll
        for (int it = 0; it < 4; it++) {
            int idx = it * 256 + tid;
            int k = idx >> 5;
            int gn = idx & 31;
            const float* src = W + (size_t)(kt + k) * ldw + gn * 4;
            cp16(Bb + k * 128 + ((gn ^ ((k << 1) & 7)) << 2), src, true);
        }
        CP_COMMIT();
    };

    int nk = K >> 5;
    stage(0, 0);
    for (int t = 0; t < nk; t++) {
        int cur = t & 1;
        if (t + 1 < nk) {
            stage(cur ^ 1, (t + 1) * 32);
            CP_WAIT(1);
        } else {
            CP_WAIT(0);
        }
        __syncthreads();

        const float* Ab = As + cur * 4096;
        const float* Bb = Bs + cur * 4096;
#pragma unroll
        for (int kc = 0; kc < 4; kc++) {
            // fragment loads with round-to-nearest tf32 conversion (fma-pipe,
            // overlapped with tensor-pipe mma) — truncation is NOT acceptable:
            // its bias compounds through 4 layers and blows the 1e-3 budget.
            uint32_t a[2][4];
#pragma unroll
            for (int mi = 0; mi < 2; mi++) {
                int r = wm * 32 + mi * 16 + (lane >> 2);
                int c = kc * 8 + (lane & 3);
                int c4 = c + 4;
                a[mi][0] = f2tf32(Ab[r * 32 + (((c >> 2) ^ (r & 7)) << 2) + (c & 3)]);
                a[mi][1] = f2tf32(Ab[(r + 8) * 32 + (((c >> 2) ^ (r & 7)) << 2) + (c & 3)]);
                a[mi][2] = f2tf32(Ab[r * 32 + (((c4 >> 2) ^ (r & 7)) << 2) + (c4 & 3)]);
                a[mi][3] = f2tf32(Ab[(r + 8) * 32 + (((c4 >> 2) ^ (r & 7)) << 2) + (c4 & 3)]);
            }
            uint32_t b[8][2];
#pragma unroll
            for (int nj = 0; nj < 8; nj++) {
                int kk = kc * 8 + (lane & 3);
                int k4 = kk + 4;
                int n = wn * 64 + nj * 8 + (lane >> 2);
                b[nj][0] = f2tf32(Bb[kk * 128 + (((n >> 2) ^ ((kk << 1) & 7)) << 2) + (n & 3)]);
                b[nj][1] = f2tf32(Bb[k4 * 128 + (((n >> 2) ^ ((k4 << 1) & 7)) << 2) + (n & 3)]);
            }
#pragma unroll
            for (int mi = 0; mi < 2; mi++)
#pragma unroll
                for (int nj = 0; nj < 8; nj++)
                    mma_tf32(acc[mi][nj], a[mi], b[nj]);
        }
        __syncthreads();
    }

    // epilogue
#pragma unroll
    for (int mi = 0; mi < 2; mi++) {
        int r = m0 + wm * 32 + mi * 16 + (lane >> 2);
#pragma unroll
        for (int nj = 0; nj < 8; nj++) {
            int cl = wn * 64 + nj * 8 + 2 * (lane & 3);
            float bx = 0.f, by = 0.f;
            if (bias) { bx = bias[cl]; by = bias[cl + 1]; }
            float2 v0 = make_float2(acc[mi][nj][0] + bx, acc[mi][nj][1] + by);
            float2 v1 = make_float2(acc[mi][nj][2] + bx, acc[mi][nj][3] + by);
            if (RELU) {
                v0.x = fmaxf(v0.x, 0.f); v0.y = fmaxf(v0.y, 0.f);
                v1.x = fmaxf(v1.x, 0.f); v1.y = fmaxf(v1.y, 0.f);
            }
            int cn = ncol0 + cl;
            if (r < M)     *(float2*)(C + (size_t)r * ldc + cn) = v0;
            if (r + 8 < M) *(float2*)(C + (size_t)(r + 8) * ldc + cn) = v1;
        }
    }
}

// ---------------- fused CSR gather + self-loop (+bias) (+relu), 128 feats ----------------
template <bool RELU>
__global__ __launch_bounds__(256)
void k_aggregate(const float* __restrict__ h, int ldh,
                 const float* __restrict__ bias,
                 float* __restrict__ out, int ldo, int n) {
    int d = (blockIdx.x * blockDim.x + threadIdx.x) >> 5;
    int lane = threadIdx.x & 31;
    if (d >= n) return;
    float disd = g_dis[d];
    int start = g_off[d];
    int end = g_off[d + 1];
    float4 acc;
    {
        float sn = disd * disd;
        float4 hv = *(const float4*)(h + (size_t)d * ldh + lane * 4);
        acc = make_float4(hv.x * sn, hv.y * sn, hv.z * sn, hv.w * sn);
    }
    for (int j = start; j < end; j++) {
        int s = g_csr_src[j];
        float nrm = disd * g_dis[s];
        float4 hv = *(const float4*)(h + (size_t)s * ldh + lane * 4);
        acc.x += hv.x * nrm;
        acc.y += hv.y * nrm;
        acc.z += hv.z * nrm;
        acc.w += hv.w * nrm;
    }
    float4 bb = make_float4(0.f, 0.f, 0.f, 0.f);
    if (bias) bb = *(const float4*)(bias + lane * 4);
    float4 r = make_float4(acc.x + bb.x, acc.y + bb.y, acc.z + bb.z, acc.w + bb.w);
    if (RELU) {
        r.x = fmaxf(r.x, 0.f);
        r.y = fmaxf(r.y, 0.f);
        r.z = fmaxf(r.z, 0.f);
        r.w = fmaxf(r.w, 0.f);
    }
    *(float4*)(out + (size_t)d * ldo + lane * 4) = r;
}

// ---------------- pooling ----------------
__global__ void k_zero_pool(float* __restrict__ out, int total, int G) {
    int i = blockIdx.x * blockDim.x + threadIdx.x;
    if (i < total) out[i] = 0.f;
    if (i < G) g_cnt[i] = 0.f;
}

__global__ __launch_bounds__(128)
void k_pool(const float* __restrict__ P, int ldp,
            const float* __restrict__ Q, int ldq,
            const int* __restrict__ batch, float* __restrict__ out, int n) {
    int f = threadIdx.x;
    int base = blockIdx.x * 256;
    float acc = 0.f;
    float cnt = 0.f;
    int cur = -1;
    for (int k = 0; k < 256; k++) {
        int i = base + k;
        if (i >= n) break;
        int g = batch[i];
        if (g != cur) {
            if (cur >= 0) {
                atomicAdd(&out[cur * 128 + f], acc);
                if (f == 0) atomicAdd(&g_cnt[cur], cnt);
            }
            cur = g;
            acc = 0.f;
            cnt = 0.f;
        }
        acc += P[(size_t)i * ldp + f] + Q[(size_t)i * ldq + f];
        cnt += 1.f;
    }
    if (cur >= 0) {
        atomicAdd(&out[cur * 128 + f], acc);
        if (f == 0) atomicAdd(&g_cnt[cur], cnt);
    }
}

__global__ void k_div(float* __restrict__ out, int total) {
    int i = blockIdx.x * blockDim.x + threadIdx.x;
    if (i < total) {
        int g = i >> 7;
        out[i] /= fmaxf(g_cnt[g], 1.0f);
    }
}

// ---------------- launch ----------------
extern "C" void kernel_launch(void* const* d_in, const int* in_sizes, int n_in,
                              void* d_out, int out_size) {
    const float* x     = (const float*)d_in[0];
    const int*   ei    = (const int*)d_in[1];
    const int*   batch = (const int*)d_in[2];
    const float* W1 = (const float*)d_in[3];
    const float* b1 = (const float*)d_in[4];
    const float* W2 = (const float*)d_in[5];
    const float* b2 = (const float*)d_in[6];
    const float* W3 = (const float*)d_in[7];
    const float* b3 = (const float*)d_in[8];
    const float* W4 = (const float*)d_in[9];
    const float* b4 = (const float*)d_in[10];
    const float* Wl = (const float*)d_in[11];
    const float* bl = (const float*)d_in[12];
    float* out = (float*)d_out;

    const int F = 128;
    int N = in_sizes[0] / F;
    int E = in_sizes[1] / 2;
    int G = out_size / 128;

    float *bufA = nullptr, *bufB = nullptr;
    cudaGetSymbolAddress((void**)&bufA, g_bufA);
    cudaGetSymbolAddress((void**)&bufB, g_bufB);

    const int SMEM = 2 * 4096 * 2 * (int)sizeof(float);  // 64 KB
    static bool attr_set = false;
    if (!attr_set) {
        cudaFuncSetAttribute(k_gemm_tf32<false>, cudaFuncAttributeMaxDynamicSharedMemorySize, SMEM);
        cudaFuncSetAttribute(k_gemm_tf32<true>, cudaFuncAttributeMaxDynamicSharedMemorySize, SMEM);
        attr_set = true;
    }

    // ---- CSR build + normalization ----
    k_zero_hist<<<(N + 255) / 256, 256>>>(N);
    k_hist<<<(E + 255) / 256, 256>>>(ei, E);
    int nb = (N + 1023) / 1024;
    k_scan1<<<nb, 256>>>(N);
    k_scan2<<<1, 1024>>>(nb);
    k_scan3<<<nb, 256>>>(N, E);
    k_fill<<<(E + 255) / 256, 256>>>(ei, E);

    int MB = (N + 127) / 128;
    int aggBlocks = (N * 32 + 255) / 256;

    // ---- G1: fused x@[W1 | Wl(+bl)] -> bufA (N x 256) ----
    k_gemm_tf32<false><<<dim3(MB, 2), 256, SMEM>>>(x, 128, 128, W1, Wl, 128,
                                                   nullptr, bl, bufA, 256, N);
    // ---- A1: agg(bufA[:,0:128]) + b1, relu -> bufB (N x 128) ----
    k_aggregate<true><<<aggBlocks, 256>>>(bufA, 256, b1, bufB, 128, N);
    // ---- G2: bufB @ W2 -> bufA[:,0:128] ----
    k_gemm_tf32<false><<<dim3(MB, 1), 256, SMEM>>>(bufB, 128, 128, W2, nullptr, 128,
                                                   nullptr, nullptr, bufA, 256, N);
    // ---- A2: agg + b2, relu -> bufB ----
    k_aggregate<true><<<aggBlocks, 256>>>(bufA, 256, b2, bufB, 128, N);
    // ---- A3 (reordered): agg(bufB) -> bufA[:,0:128] ----
    k_aggregate<false><<<aggBlocks, 256>>>(bufB, 128, nullptr, bufA, 256, N);
    // ---- G3: bufA[:,0:128] @ W3 + b3, relu -> bufB (N x 256) ----
    k_gemm_tf32<true><<<dim3(MB, 2), 256, SMEM>>>(bufA, 256, 128, W3, W3 + 128, 256,
                                                  b3, b3 + 128, bufB, 256, N);
    // ---- G4: bufB @ W4 -> bufA[:,0:128] ----
    k_gemm_tf32<false><<<dim3(MB, 1), 256, SMEM>>>(bufB, 256, 256, W4, nullptr, 128,
                                                   nullptr, nullptr, bufA, 256, N);
    // ---- A4: agg + b4 -> bufB ----
    k_aggregate<false><<<aggBlocks, 256>>>(bufA, 256, b4, bufB, 128, N);

    // ---- global mean pool: (bufB + residual in bufA[:,128:256]) ----
    k_zero_pool<<<(out_size + 255) / 256, 256>>>(out, out_size, G);
    k_pool<<<(N + 255) / 256, 128>>>(bufB, 128, bufA + 128, 256, batch, out, N);
    k_div<<<(out_size + 255) / 256, 256>>>(out, out_size);
}

// round 6
// speedup vs baseline: 1.9859x; 1.0416x over previous
#include <cuda_runtime.h>
#include <cuda_fp16.h>
#include <cstdint>

// ---------------- problem-size bounds ----------------
#define MAXN 100000
#define MAXE 1600000
#define MAXG 64
#define MAXB ((MAXN + 1023) / 1024)

// ---------------- scratch (device globals: allocation-free) ----------------
__device__ float  g_f32a[(size_t)MAXN * 128];   // residual (x@Wl+bl)
__device__ float  g_f32b[(size_t)MAXN * 128];   // fp32 ping (GEMM inputs)
__device__ float  g_f32c[(size_t)MAXN * 256];   // wide fp32 (G3 out)
__device__ __half g_f16a[(size_t)MAXN * 128];   // fp16 gather buffers
__device__ __half g_f16b[(size_t)MAXN * 128];
__device__ float  g_dis[MAXN];
__device__ int    g_hist[MAXN];
__device__ int    g_off[MAXN + 1];
__device__ int    g_cursor[MAXN];
__device__ int    g_csr_src[MAXE];
__device__ float  g_cnt[MAXG];
__device__ int    g_bsum[MAXB];
__device__ int    g_boff[MAXB];

// ---------------- CSR build ----------------
__global__ void k_zero_hist(int n) {
    int i = blockIdx.x * blockDim.x + threadIdx.x;
    if (i < n) g_hist[i] = 0;
}

__global__ void k_hist(const int* __restrict__ ei, int E) {
    int e = blockIdx.x * blockDim.x + threadIdx.x;
    if (e < E) atomicAdd(&g_hist[ei[E + e]], 1);
}

__global__ __launch_bounds__(256) void k_scan1(int n) {
    int b = blockIdx.x, t = threadIdx.x;
    int base = b * 1024;
    int s = 0;
    for (int i = t; i < 1024; i += 256) {
        int idx = base + i;
        if (idx < n) s += g_hist[idx];
    }
    __shared__ int sh[256];
    sh[t] = s;
    __syncthreads();
    for (int o = 128; o > 0; o >>= 1) {
        if (t < o) sh[t] += sh[t + o];
        __syncthreads();
    }
    if (t == 0) g_bsum[b] = sh[0];
}

__global__ __launch_bounds__(1024) void k_scan2(int nb) {
    __shared__ int sh[1024];
    int t = threadIdx.x;
    int v = (t < nb) ? g_bsum[t] : 0;
    sh[t] = v;
    __syncthreads();
    for (int o = 1; o < 1024; o <<= 1) {
        int u = (t >= o) ? sh[t - o] : 0;
        __syncthreads();
        sh[t] += u;
        __syncthreads();
    }
    if (t < nb) g_boff[t] = sh[t] - v;
}

__global__ __launch_bounds__(256) void k_scan3(int n, int E) {
    int b = blockIdx.x, t = threadIdx.x;
    int base = b * 1024 + t * 4;
    int v[4];
    int s = 0;
#pragma unroll
    for (int i = 0; i < 4; i++) {
        int idx = base + i;
        v[i] = (idx < n) ? g_hist[idx] : 0;
        s += v[i];
    }
    __shared__ int sh[256];
    sh[t] = s;
    __syncthreads();
    for (int o = 1; o < 256; o <<= 1) {
        int u = (t >= o) ? sh[t - o] : 0;
        __syncthreads();
        sh[t] += u;
        __syncthreads();
    }
    int excl = sh[t] - s + g_boff[b];
#pragma unroll
    for (int i = 0; i < 4; i++) {
        int idx = base + i;
        if (idx < n) {
            g_off[idx] = excl;
            g_cursor[idx] = excl;
            g_dis[idx] = rsqrtf((float)v[i] + 1.0f);
        }
        excl += v[i];
    }
    if (b == 0 && t == 0) g_off[n] = E;
}

__global__ void k_fill(const int* __restrict__ ei, int E) {
    int e = blockIdx.x * blockDim.x + threadIdx.x;
    if (e < E) {
        int s = ei[e];
        int d = ei[E + e];
        int pos = atomicAdd(&g_cursor[d], 1);
        g_csr_src[pos] = s;
    }
}

// ---------------- typed store helpers ----------------
__device__ __forceinline__ void st2(float* p, float2 v) { *(float2*)p = v; }
__device__ __forceinline__ void st2(__half* p, float2 v) {
    *(__half2*)p = __floats2half2_rn(v.x, v.y);
}
__device__ __forceinline__ void st4(float* p, float4 v) { *(float4*)p = v; }
__device__ __forceinline__ void st4(__half* p, float4 v) {
    __half2 a = __floats2half2_rn(v.x, v.y);
    __half2 b = __floats2half2_rn(v.z, v.w);
    uint2 u;
    u.x = *(uint32_t*)&a;
    u.y = *(uint32_t*)&b;
    *(uint2*)p = u;
}

// ---------------- TF32 tensor-core GEMM, cp.async double-buffered ----------------
__device__ __forceinline__ void mma_tf32(float* d, const uint32_t* a, const uint32_t* b) {
    asm volatile(
        "mma.sync.aligned.m16n8k8.row.col.f32.tf32.tf32.f32 "
        "{%0,%1,%2,%3}, {%4,%5,%6,%7}, {%8,%9}, {%0,%1,%2,%3};"
        : "+f"(d[0]), "+f"(d[1]), "+f"(d[2]), "+f"(d[3])
        : "r"(a[0]), "r"(a[1]), "r"(a[2]), "r"(a[3]), "r"(b[0]), "r"(b[1]));
}

__device__ __forceinline__ uint32_t f2tf32(float f) {
    uint32_t r;
    asm("cvt.rna.tf32.f32 %0, %1;" : "=r"(r) : "f"(f));
    return r;
}

__device__ __forceinline__ void cp16(float* dst, const float* src, bool pred) {
    uint32_t d = (uint32_t)__cvta_generic_to_shared(dst);
    int sz = pred ? 16 : 0;
    asm volatile("cp.async.cg.shared.global [%0], [%1], 16, %2;\n"
                 :: "r"(d), "l"(src), "r"(sz));
}
#define CP_COMMIT() asm volatile("cp.async.commit_group;\n" ::)
#define CP_WAIT(N)  asm volatile("cp.async.wait_group %0;\n" :: "n"(N))

// Block tile 128x128, BK=32, 8 warps (4m x 2n). grid.y selects weight set and
// output pointer/type (dual-weight fusion; outputs may be fp16 gather buffers).
template <bool RELU, typename T0, typename T1>
__global__ __launch_bounds__(256)
void k_gemm_tf32(const float* __restrict__ A, int lda, int K,
                 const float* __restrict__ W0, const float* __restrict__ W1p, int ldw,
                 const float* __restrict__ b0, const float* __restrict__ b1p,
                 T0* __restrict__ C0, int ldc0, T1* __restrict__ C1, int ldc1, int M) {
    extern __shared__ float smem[];
    float* As = smem;                 // [2][128*32] swizzled fp32
    float* Bs = smem + 2 * 128 * 32;  // [2][32*128] swizzled fp32

    int tid = threadIdx.x;
    int lane = tid & 31;
    int w = tid >> 5;
    int wm = w & 3;
    int wn = w >> 2;
    int m0 = blockIdx.x * 128;
    const float* W = (blockIdx.y == 0) ? W0 : W1p;
    const float* bias = (blockIdx.y == 0) ? b0 : b1p;

    float acc[2][8][4];
#pragma unroll
    for (int mi = 0; mi < 2; mi++)
#pragma unroll
        for (int nj = 0; nj < 8; nj++)
#pragma unroll
            for (int q = 0; q < 4; q++) acc[mi][nj][q] = 0.f;

    auto stage = [&](int buf, int kt) {
        float* Ab = As + buf * 4096;
        float* Bb = Bs + buf * 4096;
#pragma unroll
        for (int it = 0; it < 4; it++) {
            int idx = it * 256 + tid;
            int m = idx >> 3;
            int gk = idx & 7;
            bool pred = (m0 + m) < M;
            const float* src = pred ? (A + (size_t)(m0 + m) * lda + kt + gk * 4) : A;
            cp16(Ab + m * 32 + ((gk ^ (m & 7)) << 2), src, pred);
        }
#pragma unroll
        for (int it = 0; it < 4; it++) {
            int idx = it * 256 + tid;
            int k = idx >> 5;
            int gn = idx & 31;
            const float* src = W + (size_t)(kt + k) * ldw + gn * 4;
            cp16(Bb + k * 128 + ((gn ^ ((k << 1) & 7)) << 2), src, true);
        }
        CP_COMMIT();
    };

    int nk = K >> 5;
    stage(0, 0);
    for (int t = 0; t < nk; t++) {
        int cur = t & 1;
        if (t + 1 < nk) {
            stage(cur ^ 1, (t + 1) * 32);
            CP_WAIT(1);
        } else {
            CP_WAIT(0);
        }
        __syncthreads();

        const float* Ab = As + cur * 4096;
        const float* Bb = Bs + cur * 4096;
#pragma unroll
        for (int kc = 0; kc < 4; kc++) {
            // round-to-nearest tf32 conversion at fragment load (fma-pipe,
            // overlapped with tensor-pipe mma). Truncation is NOT acceptable:
            // its bias compounds through 4 layers and blows the 1e-3 budget.
            uint32_t a[2][4];
#pragma unroll
            for (int mi = 0; mi < 2; mi++) {
                int r = wm * 32 + mi * 16 + (lane >> 2);
                int c = kc * 8 + (lane & 3);
                int c4 = c + 4;
                a[mi][0] = f2tf32(Ab[r * 32 + (((c >> 2) ^ (r & 7)) << 2) + (c & 3)]);
                a[mi][1] = f2tf32(Ab[(r + 8) * 32 + (((c >> 2) ^ (r & 7)) << 2) + (c & 3)]);
                a[mi][2] = f2tf32(Ab[r * 32 + (((c4 >> 2) ^ (r & 7)) << 2) + (c4 & 3)]);
                a[mi][3] = f2tf32(Ab[(r + 8) * 32 + (((c4 >> 2) ^ (r & 7)) << 2) + (c4 & 3)]);
            }
            uint32_t b[8][2];
#pragma unroll
            for (int nj = 0; nj < 8; nj++) {
                int kk = kc * 8 + (lane & 3);
                int k4 = kk + 4;
                int n = wn * 64 + nj * 8 + (lane >> 2);
                b[nj][0] = f2tf32(Bb[kk * 128 + (((n >> 2) ^ ((kk << 1) & 7)) << 2) + (n & 3)]);
                b[nj][1] = f2tf32(Bb[k4 * 128 + (((n >> 2) ^ ((k4 << 1) & 7)) << 2) + (n & 3)]);
            }
#pragma unroll
            for (int mi = 0; mi < 2; mi++)
#pragma unroll
                for (int nj = 0; nj < 8; nj++)
                    mma_tf32(acc[mi][nj], a[mi], b[nj]);
        }
        __syncthreads();
    }

    // epilogue: per-y output pointer/type
#pragma unroll
    for (int mi = 0; mi < 2; mi++) {
        int r = m0 + wm * 32 + mi * 16 + (lane >> 2);
#pragma unroll
        for (int nj = 0; nj < 8; nj++) {
            int cl = wn * 64 + nj * 8 + 2 * (lane & 3);
            float bx = 0.f, by = 0.f;
            if (bias) { bx = bias[cl]; by = bias[cl + 1]; }
            float2 v0 = make_float2(acc[mi][nj][0] + bx, acc[mi][nj][1] + by);
            float2 v1 = make_float2(acc[mi][nj][2] + bx, acc[mi][nj][3] + by);
            if (RELU) {
                v0.x = fmaxf(v0.x, 0.f); v0.y = fmaxf(v0.y, 0.f);
                v1.x = fmaxf(v1.x, 0.f); v1.y = fmaxf(v1.y, 0.f);
            }
            if (blockIdx.y == 0) {
                if (r < M)     st2(C0 + (size_t)r * ldc0 + cl, v0);
                if (r + 8 < M) st2(C0 + (size_t)(r + 8) * ldc0 + cl, v1);
            } else {
                if (r < M)     st2(C1 + (size_t)r * ldc1 + cl, v0);
                if (r + 8 < M) st2(C1 + (size_t)(r + 8) * ldc1 + cl, v1);
            }
        }
    }
}

// ---------------- fused CSR gather (fp16 rows) + self-loop (+bias) (+relu) ----------------
template <bool RELU, typename OutT>
__global__ __launch_bounds__(256)
void k_aggregate(const __half* __restrict__ h, int ldh,
                 const float* __restrict__ bias,
                 OutT* __restrict__ out, int ldo, int n) {
    int d = (blockIdx.x * blockDim.x + threadIdx.x) >> 5;
    int lane = threadIdx.x & 31;
    if (d >= n) return;
    float disd = g_dis[d];
    int start = g_off[d];
    int end = g_off[d + 1];
    float4 acc;
    {
        float sn = disd * disd;
        uint2 v = *((const uint2*)(h + (size_t)d * ldh) + lane);
        float2 f01 = __half22float2(*(__half2*)&v.x);
        float2 f23 = __half22float2(*(__half2*)&v.y);
        acc = make_float4(f01.x * sn, f01.y * sn, f23.x * sn, f23.y * sn);
    }
    for (int j = start; j < end; j++) {
        int s = g_csr_src[j];
        float nrm = disd * g_dis[s];
        uint2 v = *((const uint2*)(h + (size_t)s * ldh) + lane);
        float2 f01 = __half22float2(*(__half2*)&v.x);
        float2 f23 = __half22float2(*(__half2*)&v.y);
        acc.x += f01.x * nrm;
        acc.y += f01.y * nrm;
        acc.z += f23.x * nrm;
        acc.w += f23.y * nrm;
    }
    float4 bb = make_float4(0.f, 0.f, 0.f, 0.f);
    if (bias) bb = *(const float4*)(bias + lane * 4);
    float4 r = make_float4(acc.x + bb.x, acc.y + bb.y, acc.z + bb.z, acc.w + bb.w);
    if (RELU) {
        r.x = fmaxf(r.x, 0.f);
        r.y = fmaxf(r.y, 0.f);
        r.z = fmaxf(r.z, 0.f);
        r.w = fmaxf(r.w, 0.f);
    }
    st4(out + (size_t)d * ldo + lane * 4, r);
}

// ---------------- pooling ----------------
__global__ void k_zero_pool(float* __restrict__ out, int total, int G) {
    int i = blockIdx.x * blockDim.x + threadIdx.x;
    if (i < total) out[i] = 0.f;
    if (i < G) g_cnt[i] = 0.f;
}

__global__ __launch_bounds__(128)
void k_pool(const float* __restrict__ P, int ldp,
            const float* __restrict__ Q, int ldq,
            const int* __restrict__ batch, float* __restrict__ out, int n) {
    int f = threadIdx.x;
    int base = blockIdx.x * 256;
    float acc = 0.f;
    float cnt = 0.f;
    int cur = -1;
    for (int k = 0; k < 256; k++) {
        int i = base + k;
        if (i >= n) break;
        int g = batch[i];
        if (g != cur) {
            if (cur >= 0) {
                atomicAdd(&out[cur * 128 + f], acc);
                if (f == 0) atomicAdd(&g_cnt[cur], cnt);
            }
            cur = g;
            acc = 0.f;
            cnt = 0.f;
        }
        acc += P[(size_t)i * ldp + f] + Q[(size_t)i * ldq + f];
        cnt += 1.f;
    }
    if (cur >= 0) {
        atomicAdd(&out[cur * 128 + f], acc);
        if (f == 0) atomicAdd(&g_cnt[cur], cnt);
    }
}

__global__ void k_div(float* __restrict__ out, int total) {
    int i = blockIdx.x * blockDim.x + threadIdx.x;
    if (i < total) {
        int g = i >> 7;
        out[i] /= fmaxf(g_cnt[g], 1.0f);
    }
}

// ---------------- launch ----------------
extern "C" void kernel_launch(void* const* d_in, const int* in_sizes, int n_in,
                              void* d_out, int out_size) {
    const float* x     = (const float*)d_in[0];
    const int*   ei    = (const int*)d_in[1];
    const int*   batch = (const int*)d_in[2];
    const float* W1 = (const float*)d_in[3];
    const float* b1 = (const float*)d_in[4];
    const float* W2 = (const float*)d_in[5];
    const float* b2 = (const float*)d_in[6];
    const float* W3 = (const float*)d_in[7];
    const float* b3 = (const float*)d_in[8];
    const float* W4 = (const float*)d_in[9];
    const float* b4 = (const float*)d_in[10];
    const float* Wl = (const float*)d_in[11];
    const float* bl = (const float*)d_in[12];
    float* out = (float*)d_out;

    const int F = 128;
    int N = in_sizes[0] / F;
    int E = in_sizes[1] / 2;
    int G = out_size / 128;

    float *f32a, *f32b, *f32c;
    __half *f16a, *f16b;
    cudaGetSymbolAddress((void**)&f32a, g_f32a);
    cudaGetSymbolAddress((void**)&f32b, g_f32b);
    cudaGetSymbolAddress((void**)&f32c, g_f32c);
    cudaGetSymbolAddress((void**)&f16a, g_f16a);
    cudaGetSymbolAddress((void**)&f16b, g_f16b);

    const int SMEM = 2 * 4096 * 2 * (int)sizeof(float);  // 64 KB
    static bool attr_set = false;
    if (!attr_set) {
        cudaFuncSetAttribute(k_gemm_tf32<false, __half, float>,
                             cudaFuncAttributeMaxDynamicSharedMemorySize, SMEM);
        cudaFuncSetAttribute(k_gemm_tf32<false, __half, __half>,
                             cudaFuncAttributeMaxDynamicSharedMemorySize, SMEM);
        cudaFuncSetAttribute(k_gemm_tf32<true, float, float>,
                             cudaFuncAttributeMaxDynamicSharedMemorySize, SMEM);
        attr_set = true;
    }

    // ---- CSR build + normalization ----
    k_zero_hist<<<(N + 255) / 256, 256>>>(N);
    k_hist<<<(E + 255) / 256, 256>>>(ei, E);
    int nb = (N + 1023) / 1024;
    k_scan1<<<nb, 256>>>(N);
    k_scan2<<<1, 1024>>>(nb);
    k_scan3<<<nb, 256>>>(N, E);
    k_fill<<<(E + 255) / 256, 256>>>(ei, E);

    int MB = (N + 127) / 128;
    int aggBlocks = (N * 32 + 255) / 256;

    // ---- G1: x@[W1 -> f16a | Wl(+bl) -> f32a] ----
    k_gemm_tf32<false, __half, float><<<dim3(MB, 2), 256, SMEM>>>(
        x, 128, 128, W1, Wl, 128, nullptr, bl, f16a, 128, f32a, 128, N);
    // ---- A1: agg(f16a) + b1, relu -> f32b ----
    k_aggregate<true, float><<<aggBlocks, 256>>>(f16a, 128, b1, f32b, 128, N);
    // ---- G2: f32b @ W2 -> f16b ----
    k_gemm_tf32<false, __half, __half><<<dim3(MB, 1), 256, SMEM>>>(
        f32b, 128, 128, W2, nullptr, 128, nullptr, nullptr, f16b, 128, (__half*)nullptr, 128, N);
    // ---- A2: agg(f16b) + b2, relu -> f16a ----
    k_aggregate<true, __half><<<aggBlocks, 256>>>(f16b, 128, b2, f16a, 128, N);
    // ---- A3 (reordered): agg(f16a) -> f32b ----
    k_aggregate<false, float><<<aggBlocks, 256>>>(f16a, 128, nullptr, f32b, 128, N);
    // ---- G3: f32b @ W3 + b3, relu -> f32c (N x 256) ----
    k_gemm_tf32<true, float, float><<<dim3(MB, 2), 256, SMEM>>>(
        f32b, 128, 128, W3, W3 + 128, 256, b3, b3 + 128, f32c, 256, f32c + 128, 256, N);
    // ---- G4: f32c @ W4 -> f16b ----
    k_gemm_tf32<false, __half, __half><<<dim3(MB, 1), 256, SMEM>>>(
        f32c, 256, 256, W4, nullptr, 128, nullptr, nullptr, f16b, 128, (__half*)nullptr, 128, N);
    // ---- A4: agg(f16b) + b4 -> f32b ----
    k_aggregate<false, float><<<aggBlocks, 256>>>(f16b, 128, b4, f32b, 128, N);

    // ---- global mean pool: f32b (conv out) + f32a (residual) ----
    k_zero_pool<<<(out_size + 255) / 256, 256>>>(out, out_size, G);
    k_pool<<<(N + 255) / 256, 128>>>(f32b, 128, f32a, 128, batch, out, N);
    k_div<<<(out_size + 255) / 256, 256>>>(out, out_size);
}

// round 8
// speedup vs baseline: 2.1085x; 1.0617x over previous
#include <cuda_runtime.h>
#include <cuda_fp16.h>
#include <cstdint>

// ---------------- problem-size bounds ----------------
#define MAXN 100000
#define MAXE 1600000
#define MAXG 64
#define MAXB ((MAXN + 1023) / 1024)

// ---------------- scratch (device globals: allocation-free) ----------------
__device__ __half g_xh[(size_t)MAXN * 128];     // x in fp16
__device__ __half g_f16a[(size_t)MAXN * 128];   // fp16 ping
__device__ __half g_f16b[(size_t)MAXN * 128];   // fp16 pong
__device__ __half g_f16c[(size_t)MAXN * 256];   // wide fp16 (G3 out)
__device__ __half g_wt[114688];                  // fp16 transposed weights [N][K]
__device__ float  g_f32a[(size_t)MAXN * 128];   // residual (x@Wl+bl)
__device__ float  g_f32b[(size_t)MAXN * 128];   // A4 out (pool input)
__device__ float  g_dis[MAXN];
__device__ int    g_hist[MAXN];
__device__ int    g_off[MAXN + 1];
__device__ int    g_cursor[MAXN];
__device__ int    g_csr_src[MAXE];
__device__ float  g_cnt[MAXG];
__device__ int    g_bsum[MAXB];
__device__ int    g_boff[MAXB];

// Wt offsets (halfs): Wt1@0 [128x128], Wt2@16384, Wt3@32768 [256x128],
// Wt4@65536 [128x256], Wtl@98304 [128x128]
#define WT1 0
#define WT2 16384
#define WT3 32768
#define WT4 65536
#define WTL 98304

// ---------------- input conversion ----------------
__global__ void k_cvt_x(const float* __restrict__ x, __half* __restrict__ xh, int total4) {
    int i = blockIdx.x * blockDim.x + threadIdx.x;
    if (i >= total4) return;
    float4 v = ((const float4*)x)[i];
    __half2 a = __floats2half2_rn(v.x, v.y);
    __half2 b = __floats2half2_rn(v.z, v.w);
    uint2 u;
    u.x = *(uint32_t*)&a;
    u.y = *(uint32_t*)&b;
    ((uint2*)xh)[i] = u;
}

// transpose + convert all 5 weight matrices: Wt[n*K + k] = W[k*N + n]
__global__ void k_cvt_w(const float* __restrict__ W1, const float* __restrict__ W2,
                        const float* __restrict__ W3, const float* __restrict__ W4,
                        const float* __restrict__ Wl) {
    int i = blockIdx.x * blockDim.x + threadIdx.x;
    if (i >= 114688) return;
    const float* W;
    int K, Nn, local;
    if (i < 16384)       { W = W1; K = 128; Nn = 128; local = i; }
    else if (i < 32768)  { W = W2; K = 128; Nn = 128; local = i - 16384; }
    else if (i < 65536)  { W = W3; K = 128; Nn = 256; local = i - 32768; }
    else if (i < 98304)  { W = W4; K = 256; Nn = 128; local = i - 65536; }
    else                 { W = Wl; K = 128; Nn = 128; local = i - 98304; }
    int n = local / K;
    int k = local % K;
    g_wt[i] = __float2half_rn(W[(size_t)k * Nn + n]);
}

// ---------------- CSR build ----------------
__global__ void k_zero_hist(int n) {
    int i = blockIdx.x * blockDim.x + threadIdx.x;
    if (i < n) g_hist[i] = 0;
}

__global__ void k_hist(const int* __restrict__ ei, int E) {
    int e = blockIdx.x * blockDim.x + threadIdx.x;
    if (e < E) atomicAdd(&g_hist[ei[E + e]], 1);
}

__global__ __launch_bounds__(256) void k_scan1(int n) {
    int b = blockIdx.x, t = threadIdx.x;
    int base = b * 1024;
    int s = 0;
    for (int i = t; i < 1024; i += 256) {
        int idx = base + i;
        if (idx < n) s += g_hist[idx];
    }
    __shared__ int sh[256];
    sh[t] = s;
    __syncthreads();
    for (int o = 128; o > 0; o >>= 1) {
        if (t < o) sh[t] += sh[t + o];
        __syncthreads();
    }
    if (t == 0) g_bsum[b] = sh[0];
}

__global__ __launch_bounds__(1024) void k_scan2(int nb) {
    __shared__ int sh[1024];
    int t = threadIdx.x;
    int v = (t < nb) ? g_bsum[t] : 0;
    sh[t] = v;
    __syncthreads();
    for (int o = 1; o < 1024; o <<= 1) {
        int u = (t >= o) ? sh[t - o] : 0;
        __syncthreads();
        sh[t] += u;
        __syncthreads();
    }
    if (t < nb) g_boff[t] = sh[t] - v;
}

__global__ __launch_bounds__(256) void k_scan3(int n, int E) {
    int b = blockIdx.x, t = threadIdx.x;
    int base = b * 1024 + t * 4;
    int v[4];
    int s = 0;
#pragma unroll
    for (int i = 0; i < 4; i++) {
        int idx = base + i;
        v[i] = (idx < n) ? g_hist[idx] : 0;
        s += v[i];
    }
    __shared__ int sh[256];
    sh[t] = s;
    __syncthreads();
    for (int o = 1; o < 256; o <<= 1) {
        int u = (t >= o) ? sh[t - o] : 0;
        __syncthreads();
        sh[t] += u;
        __syncthreads();
    }
    int excl = sh[t] - s + g_boff[b];
#pragma unroll
    for (int i = 0; i < 4; i++) {
        int idx = base + i;
        if (idx < n) {
            g_off[idx] = excl;
            g_cursor[idx] = excl;
            g_dis[idx] = rsqrtf((float)v[i] + 1.0f);
        }
        excl += v[i];
    }
    if (b == 0 && t == 0) g_off[n] = E;
}

__global__ void k_fill(const int* __restrict__ ei, int E) {
    int e = blockIdx.x * blockDim.x + threadIdx.x;
    if (e < E) {
        int s = ei[e];
        int d = ei[E + e];
        int pos = atomicAdd(&g_cursor[d], 1);
        g_csr_src[pos] = s;
    }
}

// ---------------- typed store helpers ----------------
__device__ __forceinline__ void st2(float* p, float2 v) { *(float2*)p = v; }
__device__ __forceinline__ void st2(__half* p, float2 v) {
    *(__half2*)p = __floats2half2_rn(v.x, v.y);
}
__device__ __forceinline__ void st4(float* p, float4 v) { *(float4*)p = v; }
__device__ __forceinline__ void st4(__half* p, float4 v) {
    __half2 a = __floats2half2_rn(v.x, v.y);
    __half2 b = __floats2half2_rn(v.z, v.w);
    uint2 u;
    u.x = *(uint32_t*)&a;
    u.y = *(uint32_t*)&b;
    *(uint2*)p = u;
}

// ---------------- FP16 tensor-core GEMM, cp.async double-buffered ----------------
// fp16 has the same 10-bit mantissa as tf32; weight-rounding error (the only
// component that survives the graph-mean pool) is unchanged vs tf32.
__device__ __forceinline__ void mma_f16(float* d, const uint32_t* a, const uint32_t* b) {
    asm volatile(
        "mma.sync.aligned.m16n8k16.row.col.f32.f16.f16.f32 "
        "{%0,%1,%2,%3}, {%4,%5,%6,%7}, {%8,%9}, {%0,%1,%2,%3};"
        : "+f"(d[0]), "+f"(d[1]), "+f"(d[2]), "+f"(d[3])
        : "r"(a[0]), "r"(a[1]), "r"(a[2]), "r"(a[3]), "r"(b[0]), "r"(b[1]));
}

__device__ __forceinline__ void cp16h(__half* dst, const __half* src, bool pred) {
    uint32_t d = (uint32_t)__cvta_generic_to_shared(dst);
    int sz = pred ? 16 : 0;
    asm volatile("cp.async.cg.shared.global [%0], [%1], 16, %2;\n"
                 :: "r"(d), "l"(src), "r"(sz));
}
#define CP_COMMIT() asm volatile("cp.async.commit_group;\n" ::)
#define CP_WAIT(N)  asm volatile("cp.async.wait_group %0;\n" :: "n"(N))

// Block tile 128x128, BK=64, 8 warps (4m x 2n), warp tile 32x64.
// A: fp16 row-major [M][lda]; W: fp16 transposed [N][ldw] (k contiguous).
// grid.y selects weight set + output pointer/type (dual-weight fusion).
// SMEM tiles are [row][64 halfs], 16B chunks XOR-swizzled by (row&7).
template <bool RELU, typename T0, typename T1>
__global__ __launch_bounds__(256)
void k_gemm_f16(const __half* __restrict__ A, int lda, int K,
                const __half* __restrict__ W0, const __half* __restrict__ W1p, int ldw,
                const float* __restrict__ b0, const float* __restrict__ b1p,
                T0* __restrict__ C0, int ldc0, T1* __restrict__ C1, int ldc1, int M) {
    extern __shared__ __half smem[];
    __half* As = smem;                  // [2][128*64]
    __half* Bs = smem + 2 * 128 * 64;   // [2][128*64]

    int tid = threadIdx.x;
    int lane = tid & 31;
    int w = tid >> 5;
    int wm = w & 3;
    int wn = w >> 2;
    int m0 = blockIdx.x * 128;
    const __half* W = (blockIdx.y == 0) ? W0 : W1p;
    const float* bias = (blockIdx.y == 0) ? b0 : b1p;

    float acc[2][8][4];
#pragma unroll
    for (int mi = 0; mi < 2; mi++)
#pragma unroll
        for (int nj = 0; nj < 8; nj++)
#pragma unroll
            for (int q = 0; q < 4; q++) acc[mi][nj][q] = 0.f;

    auto stage = [&](int buf, int kt) {
        __half* Ab = As + buf * 8192;
        __half* Bb = Bs + buf * 8192;
#pragma unroll
        for (int it = 0; it < 4; it++) {
            int idx = it * 256 + tid;
            int r = idx >> 3;          // 0..127
            int ch = idx & 7;          // 16B chunk
            bool pred = (m0 + r) < M;
            const __half* src = pred ? (A + (size_t)(m0 + r) * lda + kt + ch * 8) : A;
            cp16h(Ab + r * 64 + ((ch ^ (r & 7)) << 3), src, pred);
        }
#pragma unroll
        for (int it = 0; it < 4; it++) {
            int idx = it * 256 + tid;
            int n = idx >> 3;          // 0..127
            int ch = idx & 7;
            const __half* src = W + (size_t)n * ldw + kt + ch * 8;
            cp16h(Bb + n * 64 + ((ch ^ (n & 7)) << 3), src, true);
        }
        CP_COMMIT();
    };

    int nk = K >> 6;                    // BK = 64
    stage(0, 0);
    for (int t = 0; t < nk; t++) {
        int cur = t & 1;
        if (t + 1 < nk) {
            stage(cur ^ 1, (t + 1) * 64);
            CP_WAIT(1);
        } else {
            CP_WAIT(0);
        }
        __syncthreads();

        const __half* Ab = As + cur * 8192;
        const __half* Bb = Bs + cur * 8192;
#pragma unroll
        for (int kc = 0; kc < 4; kc++) {    // 4 x k16
            int k0 = kc * 16 + (lane & 3) * 2;
            int c0 = k0 >> 3;                // chunk = 2*kc
            int o0 = k0 & 7;
            uint32_t a[2][4];
#pragma unroll
            for (int mi = 0; mi < 2; mi++) {
                int r = wm * 32 + mi * 16 + (lane >> 2);
                int sw = (r & 7);
                const __half* base = Ab + r * 64;
                a[mi][0] = *(const uint32_t*)(base + ((c0 ^ sw) << 3) + o0);
                a[mi][1] = *(const uint32_t*)(base + 8 * 64 + ((c0 ^ sw) << 3) + o0);
                a[mi][2] = *(const uint32_t*)(base + (((c0 + 1) ^ sw) << 3) + o0);
                a[mi][3] = *(const uint32_t*)(base + 8 * 64 + (((c0 + 1) ^ sw) << 3) + o0);
            }
            uint32_t b[8][2];
#pragma unroll
            for (int nj = 0; nj < 8; nj++) {
                int n = wn * 64 + nj * 8 + (lane >> 2);
                int sw = (n & 7);
                const __half* base = Bb + n * 64;
                b[nj][0] = *(const uint32_t*)(base + ((c0 ^ sw) << 3) + o0);
                b[nj][1] = *(const uint32_t*)(base + (((c0 + 1) ^ sw) << 3) + o0);
            }
#pragma unroll
            for (int mi = 0; mi < 2; mi++)
#pragma unroll
                for (int nj = 0; nj < 8; nj++)
                    mma_f16(acc[mi][nj], a[mi], b[nj]);
        }
        __syncthreads();
    }

    // epilogue: per-y output pointer/type
#pragma unroll
    for (int mi = 0; mi < 2; mi++) {
        int r = m0 + wm * 32 + mi * 16 + (lane >> 2);
#pragma unroll
        for (int nj = 0; nj < 8; nj++) {
            int cl = wn * 64 + nj * 8 + 2 * (lane & 3);
            float bx = 0.f, by = 0.f;
            if (bias) { bx = bias[cl]; by = bias[cl + 1]; }
            float2 v0 = make_float2(acc[mi][nj][0] + bx, acc[mi][nj][1] + by);
            float2 v1 = make_float2(acc[mi][nj][2] + bx, acc[mi][nj][3] + by);
            if (RELU) {
                v0.x = fmaxf(v0.x, 0.f); v0.y = fmaxf(v0.y, 0.f);
                v1.x = fmaxf(v1.x, 0.f); v1.y = fmaxf(v1.y, 0.f);
            }
            if (blockIdx.y == 0) {
                if (r < M)     st2(C0 + (size_t)r * ldc0 + cl, v0);
                if (r + 8 < M) st2(C0 + (size_t)(r + 8) * ldc0 + cl, v1);
            } else {
                if (r < M)     st2(C1 + (size_t)r * ldc1 + cl, v0);
                if (r + 8 < M) st2(C1 + (size_t)(r + 8) * ldc1 + cl, v1);
            }
        }
    }
}

// ---------------- fused CSR gather (fp16 rows) + self-loop (+bias) (+relu) ----------------
template <bool RELU, typename OutT>
__global__ __launch_bounds__(256)
void k_aggregate(const __half* __restrict__ h, int ldh,
                 const float* __restrict__ bias,
                 OutT* __restrict__ out, int ldo, int n) {
    int d = (blockIdx.x * blockDim.x + threadIdx.x) >> 5;
    int lane = threadIdx.x & 31;
    if (d >= n) return;
    float disd = g_dis[d];
    int start = g_off[d];
    int end = g_off[d + 1];
    float4 acc;
    {
        float sn = disd * disd;
        uint2 v = *((const uint2*)(h + (size_t)d * ldh) + lane);
        float2 f01 = __half22float2(*(__half2*)&v.x);
        float2 f23 = __half22float2(*(__half2*)&v.y);
        acc = make_float4(f01.x * sn, f01.y * sn, f23.x * sn, f23.y * sn);
    }
    for (int j = start; j < end; j++) {
        int s = g_csr_src[j];
        float nrm = disd * g_dis[s];
        uint2 v = *((const uint2*)(h + (size_t)s * ldh) + lane);
        float2 f01 = __half22float2(*(__half2*)&v.x);
        float2 f23 = __half22float2(*(__half2*)&v.y);
        acc.x += f01.x * nrm;
        acc.y += f01.y * nrm;
        acc.z += f23.x * nrm;
        acc.w += f23.y * nrm;
    }
    float4 bb = make_float4(0.f, 0.f, 0.f, 0.f);
    if (bias) bb = *(const float4*)(bias + lane * 4);
    float4 r = make_float4(acc.x + bb.x, acc.y + bb.y, acc.z + bb.z, acc.w + bb.w);
    if (RELU) {
        r.x = fmaxf(r.x, 0.f);
        r.y = fmaxf(r.y, 0.f);
        r.z = fmaxf(r.z, 0.f);
        r.w = fmaxf(r.w, 0.f);
    }
    st4(out + (size_t)d * ldo + lane * 4, r);
}

// ---------------- pooling ----------------
__global__ void k_zero_pool(float* __restrict__ out, int total, int G) {
    int i = blockIdx.x * blockDim.x + threadIdx.x;
    if (i < total) out[i] = 0.f;
    if (i < G) g_cnt[i] = 0.f;
}

__global__ __launch_bounds__(128)
void k_pool(const float* __restrict__ P, int ldp,
            const float* __restrict__ Q, int ldq,
            const int* __restrict__ batch, float* __restrict__ out, int n) {
    int f = threadIdx.x;
    int base = blockIdx.x * 256;
    float acc = 0.f;
    float cnt = 0.f;
    int cur = -1;
    for (int k = 0; k < 256; k++) {
        int i = base + k;
        if (i >= n) break;
        int g = batch[i];
        if (g != cur) {
            if (cur >= 0) {
                atomicAdd(&out[cur * 128 + f], acc);
                if (f == 0) atomicAdd(&g_cnt[cur], cnt);
            }
            cur = g;
            acc = 0.f;
            cnt = 0.f;
        }
        acc += P[(size_t)i * ldp + f] + Q[(size_t)i * ldq + f];
        cnt += 1.f;
    }
    if (cur >= 0) {
        atomicAdd(&out[cur * 128 + f], acc);
        if (f == 0) atomicAdd(&g_cnt[cur], cnt);
    }
}

__global__ void k_div(float* __restrict__ out, int total) {
    int i = blockIdx.x * blockDim.x + threadIdx.x;
    if (i < total) {
        int g = i >> 7;
        out[i] /= fmaxf(g_cnt[g], 1.0f);
    }
}

// ---------------- launch ----------------
extern "C" void kernel_launch(void* const* d_in, const int* in_sizes, int n_in,
                              void* d_out, int out_size) {
    const float* x     = (const float*)d_in[0];
    const int*   ei    = (const int*)d_in[1];
    const int*   batch = (const int*)d_in[2];
    const float* W1 = (const float*)d_in[3];
    const float* b1 = (const float*)d_in[4];
    const float* W2 = (const float*)d_in[5];
    const float* b2 = (const float*)d_in[6];
    const float* W3 = (const float*)d_in[7];
    const float* b3 = (const float*)d_in[8];
    const float* W4 = (const float*)d_in[9];
    const float* b4 = (const float*)d_in[10];
    const float* Wl = (const float*)d_in[11];
    const float* bl = (const float*)d_in[12];
    float* out = (float*)d_out;

    const int F = 128;
    int N = in_sizes[0] / F;
    int E = in_sizes[1] / 2;
    int G = out_size / 128;

    __half *xh, *f16a, *f16b, *f16c, *wt;
    float *f32a, *f32b;
    cudaGetSymbolAddress((void**)&xh, g_xh);
    cudaGetSymbolAddress((void**)&f16a, g_f16a);
    cudaGetSymbolAddress((void**)&f16b, g_f16b);
    cudaGetSymbolAddress((void**)&f16c, g_f16c);
    cudaGetSymbolAddress((void**)&wt, g_wt);
    cudaGetSymbolAddress((void**)&f32a, g_f32a);
    cudaGetSymbolAddress((void**)&f32b, g_f32b);

    const int SMEM = 4 * 8192 * (int)sizeof(__half);  // 64 KB
    static bool attr_set = false;
    if (!attr_set) {
        cudaFuncSetAttribute(k_gemm_f16<false, __half, float>,
                             cudaFuncAttributeMaxDynamicSharedMemorySize, SMEM);
        cudaFuncSetAttribute(k_gemm_f16<false, __half, __half>,
                             cudaFuncAttributeMaxDynamicSharedMemorySize, SMEM);
        cudaFuncSetAttribute(k_gemm_f16<true, __half, __half>,
                             cudaFuncAttributeMaxDynamicSharedMemorySize, SMEM);
        attr_set = true;
    }

    int MB = (N + 127) / 128;
    int aggBlocks = (N * 32 + 255) / 256;
    int nb = (N + 1023) / 1024;

    // launch order chosen so launch #5 (ncu -s 5 -c 1 capture) is the G1 GEMM
    k_cvt_w<<<(114688 + 255) / 256, 256>>>(W1, W2, W3, W4, Wl);          // 0
    k_cvt_x<<<(N * 32 + 255) / 256, 256>>>(x, xh, N * 32);               // 1
    k_zero_hist<<<(N + 255) / 256, 256>>>(N);                             // 2
    k_hist<<<(E + 255) / 256, 256>>>(ei, E);                              // 3
    k_scan1<<<nb, 256>>>(N);                                              // 4
    // ---- G1: xh@[W1 -> f16a | Wl(+bl) -> f32a] ----                    // 5 (profiled)
    k_gemm_f16<false, __half, float><<<dim3(MB, 2), 256, SMEM>>>(
        xh, 128, 128, wt + WT1, wt + WTL, 128, nullptr, bl, f16a, 128, f32a, 128, N);
    k_scan2<<<1, 1024>>>(nb);                                             // 6
    k_scan3<<<nb, 256>>>(N, E);                                           // 7
    k_fill<<<(E + 255) / 256, 256>>>(ei, E);                              // 8

    // ---- A1: agg(f16a) + b1, relu -> f16b ----
    k_aggregate<true, __half><<<aggBlocks, 256>>>(f16a, 128, b1, f16b, 128, N);
    // ---- G2: f16b @ W2 -> f16a ----
    k_gemm_f16<false, __half, __half><<<dim3(MB, 1), 256, SMEM>>>(
        f16b, 128, 128, wt + WT2, nullptr, 128, nullptr, nullptr,
        f16a, 128, (__half*)nullptr, 128, N);
    // ---- A2: agg(f16a) + b2, relu -> f16b ----
    k_aggregate<true, __half><<<aggBlocks, 256>>>(f16a, 128, b2, f16b, 128, N);
    // ---- A3 (reordered): agg(f16b) -> f16a ----
    k_aggregate<false, __half><<<aggBlocks, 256>>>(f16b, 128, nullptr, f16a, 128, N);
    // ---- G3: f16a @ W3 + b3, relu -> f16c (N x 256) ----
    k_gemm_f16<true, __half, __half><<<dim3(MB, 2), 256, SMEM>>>(
        f16a, 128, 128, wt + WT3, wt + WT3 + 128 * 128, 128, b3, b3 + 128,
        f16c, 256, f16c + 128, 256, N);
    // ---- G4: f16c @ W4 -> f16b ----
    k_gemm_f16<false, __half, __half><<<dim3(MB, 1), 256, SMEM>>>(
        f16c, 256, 256, wt + WT4, nullptr, 256, nullptr, nullptr,
        f16b, 128, (__half*)nullptr, 128, N);
    // ---- A4: agg(f16b) + b4 -> f32b ----
    k_aggregate<false, float><<<aggBlocks, 256>>>(f16b, 128, b4, f32b, 128, N);

    // ---- global mean pool: f32b (conv out) + f32a (residual) ----
    k_zero_pool<<<(out_size + 255) / 256, 256>>>(out, out_size, G);
    k_pool<<<(N + 255) / 256, 128>>>(f32b, 128, f32a, 128, batch, out, N);
    k_div<<<(out_size + 255) / 256, 256>>>(out, out_size);
}

// round 12
// speedup vs baseline: 2.2755x; 1.0792x over previous
#include <cuda_runtime.h>
#include <cuda_fp16.h>
#include <cstdint>

// ---------------- problem-size bounds ----------------
#define MAXN 100000
#define MAXE 1600000
#define MAXG 64
#define MAXB ((MAXN + 1023) / 1024)

// ---------------- scratch (device globals: allocation-free) ----------------
__device__ __half g_xh[(size_t)MAXN * 128];     // x in fp16
__device__ __half g_f16a[(size_t)MAXN * 128];   // fp16 ping
__device__ __half g_f16b[(size_t)MAXN * 128];   // fp16 pong
__device__ __half g_f16c[(size_t)MAXN * 256];   // wide fp16 (G3 out)
__device__ __half g_wt[114688];                  // fp16 transposed weights [N][K]
__device__ float  g_f32a[(size_t)MAXN * 128];   // residual (x@Wl+bl)
__device__ float  g_f32b[(size_t)MAXN * 128];   // A4 out (pool input)
__device__ float  g_dis[MAXN];
__device__ int    g_hist[MAXN];
__device__ int    g_off[MAXN + 1];
__device__ int    g_cursor[MAXN];
__device__ int    g_csr_src[MAXE];
__device__ float  g_cnt[MAXG];
__device__ int    g_bsum[MAXB];
__device__ int    g_boff[MAXB];

#define WT1 0
#define WT2 16384
#define WT3 32768
#define WT4 65536
#define WTL 98304

// ---------------- input conversion ----------------
__global__ void k_cvt_x(const float* __restrict__ x, __half* __restrict__ xh, int total4) {
    int i = blockIdx.x * blockDim.x + threadIdx.x;
    if (i >= total4) return;
    float4 v = ((const float4*)x)[i];
    __half2 a = __floats2half2_rn(v.x, v.y);
    __half2 b = __floats2half2_rn(v.z, v.w);
    uint2 u;
    u.x = *(uint32_t*)&a;
    u.y = *(uint32_t*)&b;
    ((uint2*)xh)[i] = u;
}

__global__ void k_cvt_w(const float* __restrict__ W1, const float* __restrict__ W2,
                        const float* __restrict__ W3, const float* __restrict__ W4,
                        const float* __restrict__ Wl) {
    int i = blockIdx.x * blockDim.x + threadIdx.x;
    if (i >= 114688) return;
    const float* W;
    int K, Nn, local;
    if (i < 16384)       { W = W1; K = 128; Nn = 128; local = i; }
    else if (i < 32768)  { W = W2; K = 128; Nn = 128; local = i - 16384; }
    else if (i < 65536)  { W = W3; K = 128; Nn = 256; local = i - 32768; }
    else if (i < 98304)  { W = W4; K = 256; Nn = 128; local = i - 65536; }
    else                 { W = Wl; K = 128; Nn = 128; local = i - 98304; }
    int n = local / K;
    int k = local % K;
    g_wt[i] = __float2half_rn(W[(size_t)k * Nn + n]);
}

// ---------------- CSR build ----------------
__global__ void k_zero_hist(int n) {
    int i = blockIdx.x * blockDim.x + threadIdx.x;
    if (i < n) g_hist[i] = 0;
}

__global__ void k_hist(const int* __restrict__ ei, int E) {
    int e = blockIdx.x * blockDim.x + threadIdx.x;
    if (e < E) atomicAdd(&g_hist[ei[E + e]], 1);
}

__global__ __launch_bounds__(256) void k_scan1(int n) {
    int b = blockIdx.x, t = threadIdx.x;
    int base = b * 1024;
    int s = 0;
    for (int i = t; i < 1024; i += 256) {
        int idx = base + i;
        if (idx < n) s += g_hist[idx];
    }
    __shared__ int sh[256];
    sh[t] = s;
    __syncthreads();
    for (int o = 128; o > 0; o >>= 1) {
        if (t < o) sh[t] += sh[t + o];
        __syncthreads();
    }
    if (t == 0) g_bsum[b] = sh[0];
}

__global__ __launch_bounds__(1024) void k_scan2(int nb) {
    __shared__ int sh[1024];
    int t = threadIdx.x;
    int v = (t < nb) ? g_bsum[t] : 0;
    sh[t] = v;
    __syncthreads();
    for (int o = 1; o < 1024; o <<= 1) {
        int u = (t >= o) ? sh[t - o] : 0;
        __syncthreads();
        sh[t] += u;
        __syncthreads();
    }
    if (t < nb) g_boff[t] = sh[t] - v;
}

__global__ __launch_bounds__(256) void k_scan3(int n, int E) {
    int b = blockIdx.x, t = threadIdx.x;
    int base = b * 1024 + t * 4;
    int v[4];
    int s = 0;
#pragma unroll
    for (int i = 0; i < 4; i++) {
        int idx = base + i;
        v[i] = (idx < n) ? g_hist[idx] : 0;
        s += v[i];
    }
    __shared__ int sh[256];
    sh[t] = s;
    __syncthreads();
    for (int o = 1; o < 256; o <<= 1) {
        int u = (t >= o) ? sh[t - o] : 0;
        __syncthreads();
        sh[t] += u;
        __syncthreads();
    }
    int excl = sh[t] - s + g_boff[b];
#pragma unroll
    for (int i = 0; i < 4; i++) {
        int idx = base + i;
        if (idx < n) {
            g_off[idx] = excl;
            g_cursor[idx] = excl;
            g_dis[idx] = rsqrtf((float)v[i] + 1.0f);
        }
        excl += v[i];
    }
    if (b == 0 && t == 0) g_off[n] = E;
}

__global__ void k_fill(const int* __restrict__ ei, int E) {
    int e = blockIdx.x * blockDim.x + threadIdx.x;
    if (e < E) {
        int s = ei[e];
        int d = ei[E + e];
        int pos = atomicAdd(&g_cursor[d], 1);
        g_csr_src[pos] = s;
    }
}

// ---------------- typed store helpers ----------------
__device__ __forceinline__ void st2(float* p, float2 v) { *(float2*)p = v; }
__device__ __forceinline__ void st2(__half* p, float2 v) {
    *(__half2*)p = __floats2half2_rn(v.x, v.y);
}
__device__ __forceinline__ void st4(float* p, float4 v) { *(float4*)p = v; }
__device__ __forceinline__ void st4(__half* p, float4 v) {
    __half2 a = __floats2half2_rn(v.x, v.y);
    __half2 b = __floats2half2_rn(v.z, v.w);
    uint2 u;
    u.x = *(uint32_t*)&a;
    u.y = *(uint32_t*)&b;
    *(uint2*)p = u;
}

// ---------------- FP16 tensor-core GEMM (mma.sync + ldmatrix) ----------------
__device__ __forceinline__ void mma_f16(float* d, const uint32_t* a, const uint32_t* b) {
    asm volatile(
        "mma.sync.aligned.m16n8k16.row.col.f32.f16.f16.f32 "
        "{%0,%1,%2,%3}, {%4,%5,%6,%7}, {%8,%9}, {%0,%1,%2,%3};"
        : "+f"(d[0]), "+f"(d[1]), "+f"(d[2]), "+f"(d[3])
        : "r"(a[0]), "r"(a[1]), "r"(a[2]), "r"(a[3]), "r"(b[0]), "r"(b[1]));
}

__device__ __forceinline__ void ldsm4(uint32_t& r0, uint32_t& r1, uint32_t& r2,
                                      uint32_t& r3, uint32_t addr) {
    asm volatile("ldmatrix.sync.aligned.m8n8.x4.shared.b16 {%0,%1,%2,%3}, [%4];"
                 : "=r"(r0), "=r"(r1), "=r"(r2), "=r"(r3) : "r"(addr));
}

__device__ __forceinline__ void cp16h(__half* dst, const __half* src, bool pred) {
    uint32_t d = (uint32_t)__cvta_generic_to_shared(dst);
    int sz = pred ? 16 : 0;
    asm volatile("cp.async.cg.shared.global [%0], [%1], 16, %2;\n"
                 :: "r"(d), "l"(src), "r"(sz));
}
#define CP_COMMIT() asm volatile("cp.async.commit_group;\n" ::)
#define CP_WAIT(N)  asm volatile("cp.async.wait_group %0;\n" :: "n"(N))

// Block tile 128x128, BK=64, 8 warps (4m x 2n), warp tile 32x64.
// A: fp16 row-major [M][lda]; W: fp16 transposed [N][ldw] (k contiguous).
// grid.y selects weight set + output pointer/type (dual-weight fusion).
// SMEM tiles: [row][64 halfs], 16B chunks XOR-swizzled by (row&7).
template <bool RELU, typename T0, typename T1>
__global__ __launch_bounds__(256)
void k_gemm_f16(const __half* __restrict__ A, int lda, int K,
                const __half* __restrict__ W0, const __half* __restrict__ W1p, int ldw,
                const float* __restrict__ b0, const float* __restrict__ b1p,
                T0* __restrict__ C0, int ldc0, T1* __restrict__ C1, int ldc1, int M) {
    extern __shared__ __half smem[];
    __half* As = smem;                  // [2][128*64]
    __half* Bs = smem + 2 * 128 * 64;   // [2][128*64]
    uint32_t sbase = (uint32_t)__cvta_generic_to_shared(smem);

    int tid = threadIdx.x;
    int lane = tid & 31;
    int w = tid >> 5;
    int wm = w & 3;
    int wn = w >> 2;
    int m0 = blockIdx.x * 128;
    const __half* W = (blockIdx.y == 0) ? W0 : W1p;
    const float* bias = (blockIdx.y == 0) ? b0 : b1p;

    float acc[2][8][4];
#pragma unroll
    for (int mi = 0; mi < 2; mi++)
#pragma unroll
        for (int nj = 0; nj < 8; nj++)
#pragma unroll
            for (int q = 0; q < 4; q++) acc[mi][nj][q] = 0.f;

    auto stage = [&](int buf, int kt) {
        __half* Ab = As + buf * 8192;
        __half* Bb = Bs + buf * 8192;
#pragma unroll
        for (int it = 0; it < 4; it++) {
            int idx = it * 256 + tid;
            int r = idx >> 3;          // 0..127
            int ch = idx & 7;          // 16B chunk
            bool pred = (m0 + r) < M;
            const __half* src = pred ? (A + (size_t)(m0 + r) * lda + kt + ch * 8) : A;
            cp16h(Ab + r * 64 + ((ch ^ (r & 7)) << 3), src, pred);
        }
#pragma unroll
        for (int it = 0; it < 4; it++) {
            int idx = it * 256 + tid;
            int n = idx >> 3;          // 0..127
            int ch = idx & 7;
            const __half* src = W + (size_t)n * ldw + kt + ch * 8;
            cp16h(Bb + n * 64 + ((ch ^ (n & 7)) << 3), src, true);
        }
        CP_COMMIT();
    };

    // ldmatrix lane decomposition (constant over k-loop)
    int g = lane >> 3;        // matrix group 0..3
    int lrow = lane & 7;      // row within 8x8 matrix

    int nk = K >> 6;                    // BK = 64
    stage(0, 0);
    for (int t = 0; t < nk; t++) {
        int cur = t & 1;
        if (t + 1 < nk) {
            stage(cur ^ 1, (t + 1) * 64);
            CP_WAIT(1);
        } else {
            CP_WAIT(0);
        }
        __syncthreads();

        uint32_t abase = sbase + (cur * 8192) * 2;
        uint32_t bbase = sbase + (2 * 8192 + cur * 8192) * 2;
#pragma unroll
        for (int kc = 0; kc < 4; kc++) {    // 4 x k16
            int c0 = kc * 2;                 // first 8-half chunk of this k16
            // A fragments: x4 = {rows0-7/c0, rows8-15/c0, rows0-7/c0+1, rows8-15/c0+1}
            uint32_t a[2][4];
#pragma unroll
            for (int mi = 0; mi < 2; mi++) {
                int r = wm * 32 + mi * 16 + (g & 1) * 8 + lrow;
                int ch = c0 + (g >> 1);
                uint32_t addr = abase + ((r * 64 + ((ch ^ (r & 7)) << 3)) << 1);
                ldsm4(a[mi][0], a[mi][1], a[mi][2], a[mi][3], addr);
            }
            // B fragments: x4 covers two n8 groups x two k8 chunks
            uint32_t b[8][2];
#pragma unroll
            for (int p = 0; p < 4; p++) {
                int n = wn * 64 + p * 16 + (g >> 1) * 8 + lrow;
                int ch = c0 + (g & 1);
                uint32_t addr = bbase + ((n * 64 + ((ch ^ (n & 7)) << 3)) << 1);
                ldsm4(b[2 * p][0], b[2 * p][1], b[2 * p + 1][0], b[2 * p + 1][1], addr);
            }
#pragma unroll
            for (int mi = 0; mi < 2; mi++)
#pragma unroll
                for (int nj = 0; nj < 8; nj++)
                    mma_f16(acc[mi][nj], a[mi], b[nj]);
        }
        __syncthreads();
    }

    // epilogue: per-y output pointer/type
#pragma unroll
    for (int mi = 0; mi < 2; mi++) {
        int r = m0 + wm * 32 + mi * 16 + (lane >> 2);
#pragma unroll
        for (int nj = 0; nj < 8; nj++) {
            int cl = wn * 64 + nj * 8 + 2 * (lane & 3);
            float bx = 0.f, by = 0.f;
            if (bias) { bx = bias[cl]; by = bias[cl + 1]; }
            float2 v0 = make_float2(acc[mi][nj][0] + bx, acc[mi][nj][1] + by);
            float2 v1 = make_float2(acc[mi][nj][2] + bx, acc[mi][nj][3] + by);
            if (RELU) {
                v0.x = fmaxf(v0.x, 0.f); v0.y = fmaxf(v0.y, 0.f);
                v1.x = fmaxf(v1.x, 0.f); v1.y = fmaxf(v1.y, 0.f);
            }
            if (blockIdx.y == 0) {
                if (r < M)     st2(C0 + (size_t)r * ldc0 + cl, v0);
                if (r + 8 < M) st2(C0 + (size_t)(r + 8) * ldc0 + cl, v1);
            } else {
                if (r < M)     st2(C1 + (size_t)r * ldc1 + cl, v0);
                if (r + 8 < M) st2(C1 + (size_t)(r + 8) * ldc1 + cl, v1);
            }
        }
    }
}

// ---------------- fused CSR gather (fp16 rows) + self-loop (+bias) (+relu) ----------------
template <bool RELU, typename OutT>
__global__ __launch_bounds__(256)
void k_aggregate(const __half* __restrict__ h, int ldh,
                 const float* __restrict__ bias,
                 OutT* __restrict__ out, int ldo, int n) {
    int d = (blockIdx.x * blockDim.x + threadIdx.x) >> 5;
    int lane = threadIdx.x & 31;
    if (d >= n) return;
    float disd = g_dis[d];
    int start = g_off[d];
    int end = g_off[d + 1];
    float4 acc;
    {
        float sn = disd * disd;
        uint2 v = *((const uint2*)(h + (size_t)d * ldh) + lane);
        float2 f01 = __half22float2(*(__half2*)&v.x);
        float2 f23 = __half22float2(*(__half2*)&v.y);
        acc = make_float4(f01.x * sn, f01.y * sn, f23.x * sn, f23.y * sn);
    }
    for (int j = start; j < end; j++) {
        int s = g_csr_src[j];
        float nrm = disd * g_dis[s];
        uint2 v = *((const uint2*)(h + (size_t)s * ldh) + lane);
        float2 f01 = __half22float2(*(__half2*)&v.x);
        float2 f23 = __half22float2(*(__half2*)&v.y);
        acc.x += f01.x * nrm;
        acc.y += f01.y * nrm;
        acc.z += f23.x * nrm;
        acc.w += f23.y * nrm;
    }
    float4 bb = make_float4(0.f, 0.f, 0.f, 0.f);
    if (bias) bb = *(const float4*)(bias + lane * 4);
    float4 r = make_float4(acc.x + bb.x, acc.y + bb.y, acc.z + bb.z, acc.w + bb.w);
    if (RELU) {
        r.x = fmaxf(r.x, 0.f);
        r.y = fmaxf(r.y, 0.f);
        r.z = fmaxf(r.z, 0.f);
        r.w = fmaxf(r.w, 0.f);
    }
    st4(out + (size_t)d * ldo + lane * 4, r);
}

// ---------------- pooling ----------------
__global__ void k_zero_pool(float* __restrict__ out, int total, int G) {
    int i = blockIdx.x * blockDim.x + threadIdx.x;
    if (i < total) out[i] = 0.f;
    if (i < G) g_cnt[i] = 0.f;
}

__global__ __launch_bounds__(128)
void k_pool(const float* __restrict__ P, int ldp,
            const float* __restrict__ Q, int ldq,
            const int* __restrict__ batch, float* __restrict__ out, int n) {
    int f = threadIdx.x;
    int base = blockIdx.x * 256;
    float acc = 0.f;
    float cnt = 0.f;
    int cur = -1;
    for (int k = 0; k < 256; k++) {
        int i = base + k;
        if (i >= n) break;
        int g = batch[i];
        if (g != cur) {
            if (cur >= 0) {
                atomicAdd(&out[cur * 128 + f], acc);
                if (f == 0) atomicAdd(&g_cnt[cur], cnt);
            }
            cur = g;
            acc = 0.f;
            cnt = 0.f;
        }
        acc += P[(size_t)i * ldp + f] + Q[(size_t)i * ldq + f];
        cnt += 1.f;
    }
    if (cur >= 0) {
        atomicAdd(&out[cur * 128 + f], acc);
        if (f == 0) atomicAdd(&g_cnt[cur], cnt);
    }
}

__global__ void k_div(float* __restrict__ out, int total) {
    int i = blockIdx.x * blockDim.x + threadIdx.x;
    if (i < total) {
        int g = i >> 7;
        out[i] /= fmaxf(g_cnt[g], 1.0f);
    }
}

// ---------------- launch ----------------
extern "C" void kernel_launch(void* const* d_in, const int* in_sizes, int n_in,
                              void* d_out, int out_size) {
    const float* x     = (const float*)d_in[0];
    const int*   ei    = (const int*)d_in[1];
    const int*   batch = (const int*)d_in[2];
    const float* W1 = (const float*)d_in[3];
    const float* b1 = (const float*)d_in[4];
    const float* W2 = (const float*)d_in[5];
    const float* b2 = (const float*)d_in[6];
    const float* W3 = (const float*)d_in[7];
    const float* b3 = (const float*)d_in[8];
    const float* W4 = (const float*)d_in[9];
    const float* b4 = (const float*)d_in[10];
    const float* Wl = (const float*)d_in[11];
    const float* bl = (const float*)d_in[12];
    float* out = (float*)d_out;

    const int F = 128;
    int N = in_sizes[0] / F;
    int E = in_sizes[1] / 2;
    int G = out_size / 128;

    __half *xh, *f16a, *f16b, *f16c, *wt;
    float *f32a, *f32b;
    cudaGetSymbolAddress((void**)&xh, g_xh);
    cudaGetSymbolAddress((void**)&f16a, g_f16a);
    cudaGetSymbolAddress((void**)&f16b, g_f16b);
    cudaGetSymbolAddress((void**)&f16c, g_f16c);
    cudaGetSymbolAddress((void**)&wt, g_wt);
    cudaGetSymbolAddress((void**)&f32a, g_f32a);
    cudaGetSymbolAddress((void**)&f32b, g_f32b);

    const int SMEM = 4 * 8192 * (int)sizeof(__half);  // 64 KB
    static bool attr_set = false;
    if (!attr_set) {
        cudaFuncSetAttribute(k_gemm_f16<false, __half, float>,
                             cudaFuncAttributeMaxDynamicSharedMemorySize, SMEM);
        cudaFuncSetAttribute(k_gemm_f16<false, __half, __half>,
                             cudaFuncAttributeMaxDynamicSharedMemorySize, SMEM);
        cudaFuncSetAttribute(k_gemm_f16<true, __half, __half>,
                             cudaFuncAttributeMaxDynamicSharedMemorySize, SMEM);
        attr_set = true;
    }

    int MB = (N + 127) / 128;
    int aggBlocks = (N * 32 + 255) / 256;
    int nb = (N + 1023) / 1024;

    // Our launch #3 is what ncu profiles (observed across rounds 1-8) -> G1 GEMM.
    k_cvt_w<<<(114688 + 255) / 256, 256>>>(W1, W2, W3, W4, Wl);          // 0
    k_cvt_x<<<(N * 32 + 255) / 256, 256>>>(x, xh, N * 32);               // 1
    k_zero_hist<<<(N + 255) / 256, 256>>>(N);                             // 2
    // ---- G1: xh@[W1 -> f16a | Wl(+bl) -> f32a] ----                    // 3 (profiled)
    k_gemm_f16<false, __half, float><<<dim3(MB, 2), 256, SMEM>>>(
        xh, 128, 128, wt + WT1, wt + WTL, 128, nullptr, bl, f16a, 128, f32a, 128, N);
    k_hist<<<(E + 255) / 256, 256>>>(ei, E);                              // 4
    k_scan1<<<nb, 256>>>(N);                                              // 5
    k_scan2<<<1, 1024>>>(nb);                                             // 6
    k_scan3<<<nb, 256>>>(N, E);                                           // 7
    k_fill<<<(E + 255) / 256, 256>>>(ei, E);                              // 8

    // ---- A1: agg(f16a) + b1, relu -> f16b ----
    k_aggregate<true, __half><<<aggBlocks, 256>>>(f16a, 128, b1, f16b, 128, N);
    // ---- G2: f16b @ W2 -> f16a ----
    k_gemm_f16<false, __half, __half><<<dim3(MB, 1), 256, SMEM>>>(
        f16b, 128, 128, wt + WT2, nullptr, 128, nullptr, nullptr,
        f16a, 128, (__half*)nullptr, 128, N);
    // ---- A2: agg(f16a) + b2, relu -> f16b ----
    k_aggregate<true, __half><<<aggBlocks, 256>>>(f16a, 128, b2, f16b, 128, N);
    // ---- A3 (reordered): agg(f16b) -> f16a ----
    k_aggregate<false, __half><<<aggBlocks, 256>>>(f16b, 128, nullptr, f16a, 128, N);
    // ---- G3: f16a @ W3 + b3, relu -> f16c (N x 256) ----
    k_gemm_f16<true, __half, __half><<<dim3(MB, 2), 256, SMEM>>>(
        f16a, 128, 128, wt + WT3, wt + WT3 + 128 * 128, 128, b3, b3 + 128,
        f16c, 256, f16c + 128, 256, N);
    // ---- G4: f16c @ W4 -> f16b (K=256) ----
    k_gemm_f16<false, __half, __half><<<dim3(MB, 1), 256, SMEM>>>(
        f16c, 256, 256, wt + WT4, nullptr, 256, nullptr, nullptr,
        f16b, 128, (__half*)nullptr, 128, N);
    // ---- A4: agg(f16b) + b4 -> f32b ----
    k_aggregate<false, float><<<aggBlocks, 256>>>(f16b, 128, b4, f32b, 128, N);

    // ---- global mean pool: f32b (conv out) + f32a (residual) ----
    k_zero_pool<<<(out_size + 255) / 256, 256>>>(out, out_size, G);
    k_pool<<<(N + 255) / 256, 128>>>(f32b, 128, f32a, 128, batch, out, N);
    k_div<<<(out_size + 255) / 256, 256>>>(out, out_size);
}